// round 3
// baseline (speedup 1.0000x reference)
#include <cuda_runtime.h>
#include <cuda_bf16.h>
#include <math.h>

#define B_SZ 2
#define NTOK 2048
#define NH 8
#define DK 64
#define DM 512

// Scratch (device globals; no cudaMalloc allowed)
__device__ float g_qh[B_SZ * NH * NTOK * DK];   // [b][h][n][dk], pre-scaled by 1/sqrt(dk)
__device__ float g_kh[B_SZ * NH * NTOK * DK];
__device__ float g_vh[B_SZ * NH * NTOK * DK];
__device__ float g_o [B_SZ * NTOK * DM];        // [b][n][h*64+dk]

#define INF_F __int_as_float(0x7f800000)

// ---------------------------------------------------------------------------
// Projection GEMM: for z in {q,k,v}: out[b,h,n,:] = X[b,n,:] @ proj[h]  (X:[4096,512])
// 64x64 tiles, K chunks of 32, 256 threads, 4x4 register tiles.
// ---------------------------------------------------------------------------
__global__ __launch_bounds__(256) void proj_kernel(
    const float* __restrict__ q, const float* __restrict__ k, const float* __restrict__ v,
    const float* __restrict__ qp, const float* __restrict__ kpj, const float* __restrict__ vp)
{
    __shared__ float AsT[32 * 68];   // [kk][row]
    __shared__ float Bs [32 * 68];   // [kk][col]

    const int tid = threadIdx.x;
    const int tx = tid & 15, ty = tid >> 4;
    const int h  = blockIdx.x;          // column tile == head (64-wide)
    const int r0 = blockIdx.y * 64;     // row tile into [4096]
    const int z  = blockIdx.z;

    const float* X = (z == 0) ? q : (z == 1) ? k : v;
    const float* W = (z == 0) ? qp : (z == 1) ? kpj : vp;

    float acc[4][4];
#pragma unroll
    for (int i = 0; i < 4; i++)
#pragma unroll
        for (int j = 0; j < 4; j++) acc[i][j] = 0.f;

    for (int k0 = 0; k0 < DM; k0 += 32) {
        // load A tile transposed: X[(r0+r)][k0+kk] -> AsT[kk][r]
        {
            int r = tid >> 2, j = tid & 3;
            const float4* asrc = (const float4*)(X + (size_t)(r0 + r) * DM + k0 + j * 8);
#pragma unroll
            for (int p = 0; p < 2; p++) {
                float4 a4 = asrc[p];
                int d = j * 8 + p * 4;
                AsT[(d + 0) * 68 + r] = a4.x;
                AsT[(d + 1) * 68 + r] = a4.y;
                AsT[(d + 2) * 68 + r] = a4.z;
                AsT[(d + 3) * 68 + r] = a4.w;
            }
        }
        // load B tile natural: proj[h][(k0+kk)][cc] -> Bs[kk][cc]
        {
            int kk = tid >> 3, jj = tid & 7;
            const float4* bsrc = (const float4*)(W + (size_t)h * DM * DK + (size_t)(k0 + kk) * DK + jj * 8);
            *(float4*)(Bs + kk * 68 + jj * 8)     = bsrc[0];
            *(float4*)(Bs + kk * 68 + jj * 8 + 4) = bsrc[1];
        }
        __syncthreads();
#pragma unroll
        for (int kk = 0; kk < 32; kk++) {
            float4 a = *(const float4*)(AsT + kk * 68 + 4 * ty);
            float4 b = *(const float4*)(Bs  + kk * 68 + 4 * tx);
            acc[0][0] += a.x * b.x; acc[0][1] += a.x * b.y; acc[0][2] += a.x * b.z; acc[0][3] += a.x * b.w;
            acc[1][0] += a.y * b.x; acc[1][1] += a.y * b.y; acc[1][2] += a.y * b.z; acc[1][3] += a.y * b.w;
            acc[2][0] += a.z * b.x; acc[2][1] += a.z * b.y; acc[2][2] += a.z * b.z; acc[2][3] += a.z * b.w;
            acc[3][0] += a.w * b.x; acc[3][1] += a.w * b.y; acc[3][2] += a.w * b.z; acc[3][3] += a.w * b.w;
        }
        __syncthreads();
    }

    const float scale = (z == 0) ? 0.125f : 1.0f;   // 1/sqrt(64) folded into Q
    float* dst = (z == 0) ? g_qh : (z == 1) ? g_kh : g_vh;
#pragma unroll
    for (int i = 0; i < 4; i++) {
        int row = r0 + 4 * ty + i;
        int bb = row >> 11, n = row & (NTOK - 1);
        float4 o = make_float4(acc[i][0] * scale, acc[i][1] * scale, acc[i][2] * scale, acc[i][3] * scale);
        *(float4*)(dst + (((size_t)bb * NH + h) * NTOK + n) * DK + 4 * tx) = o;
    }
}

// ---------------------------------------------------------------------------
// Fused distance-modulated flash attention.
// One block per (q-tile 64, h, b). 256 threads, 4x4 register tiles.
// ---------------------------------------------------------------------------
__global__ __launch_bounds__(256, 2) void attn_kernel(
    const float* __restrict__ coords, const unsigned char* __restrict__ kpm)
{
    extern __shared__ float sm[];
    float* qsT = sm;               // [64 dim][68]  (transposed, [d][row])
    float* ksT = sm + 4352;        // [64 dim][68]  (transposed, [d][col])
    float* vs  = sm + 8704;        // [64 m][68]    (natural)
    float* ps  = sm + 13056;       // [64 r][68]    (natural)
    float* mc  = sm + 17408;       // [64*3] m-coords
    float* kpf = sm + 17600;       // [64] key-padding flags

    const int tid = threadIdx.x;
    const int tx = tid & 15, ty = tid >> 4;
    const int b = blockIdx.z, h = blockIdx.y;
    const int q0 = blockIdx.x * 64;

    // head spread constants
    const float tpow   = 0.98f * (float)h / 7.0f;
    const float spread = 3.7f + (powf(20.0f, tpow) - 1.0f) * (16.3f / 19.0f);
    const float s2      = spread * spread;
    const float nine_s2 = 9.0f * s2;
    const float inv2s2  = 1.0f / (2.0f * s2);

    const float* qbase = g_qh + (((size_t)b * NH + h) * NTOK + q0) * DK;
    const float* kbase = g_kh + (((size_t)b * NH + h) * NTOK) * DK;
    const float* vbase = g_vh + (((size_t)b * NH + h) * NTOK) * DK;

    // load Q tile transposed (once)
    {
        int r = tid >> 2, j = tid & 3;
        const float4* src = (const float4*)(qbase + r * DK + j * 16);
#pragma unroll
        for (int p = 0; p < 4; p++) {
            float4 a4 = src[p];
            int d = j * 16 + p * 4;
            qsT[(d + 0) * 68 + r] = a4.x;
            qsT[(d + 1) * 68 + r] = a4.y;
            qsT[(d + 2) * 68 + r] = a4.z;
            qsT[(d + 3) * 68 + r] = a4.w;
        }
    }
    // q coords for my 4 rows (registers)
    float qcx[4], qcy[4], qcz[4];
#pragma unroll
    for (int i = 0; i < 4; i++) {
        const float* cp = coords + ((size_t)b * NTOK + q0 + 4 * ty + i) * 3;
        qcx[i] = cp[0]; qcy[i] = cp[1]; qcz[i] = cp[2];
    }

    float mI[4], lI[4], accO[4][4];
#pragma unroll
    for (int i = 0; i < 4; i++) {
        mI[i] = -INF_F; lI[i] = 0.f;
#pragma unroll
        for (int j = 0; j < 4; j++) accO[i][j] = 0.f;
    }

    for (int mt = 0; mt < NTOK / 64; mt++) {
        const int m0 = mt * 64;
        // --- loads ---
        {
            int r = tid >> 2, j = tid & 3;
            const float4* ksrc = (const float4*)(kbase + (size_t)(m0 + r) * DK + j * 16);
#pragma unroll
            for (int p = 0; p < 4; p++) {
                float4 a4 = ksrc[p];
                int d = j * 16 + p * 4;
                ksT[(d + 0) * 68 + r] = a4.x;
                ksT[(d + 1) * 68 + r] = a4.y;
                ksT[(d + 2) * 68 + r] = a4.z;
                ksT[(d + 3) * 68 + r] = a4.w;
            }
            const float4* vsrc = (const float4*)(vbase + (size_t)(m0 + r) * DK + j * 16);
            float4* vdst = (float4*)(vs + r * 68 + j * 16);
#pragma unroll
            for (int p = 0; p < 4; p++) vdst[p] = vsrc[p];
        }
        if (tid < 64) {
            const float* cp = coords + ((size_t)b * NTOK + m0 + tid) * 3;
            mc[tid * 3 + 0] = cp[0];
            mc[tid * 3 + 1] = cp[1];
            mc[tid * 3 + 2] = cp[2];
            kpf[tid] = kpm[(size_t)b * NTOK + m0 + tid] ? 1.f : 0.f;
        }
        __syncthreads();

        // --- S = Q Kt (scaled logits; scale already folded into Q) ---
        float acc[4][4];
#pragma unroll
        for (int i = 0; i < 4; i++)
#pragma unroll
            for (int j = 0; j < 4; j++) acc[i][j] = 0.f;
#pragma unroll 4
        for (int kk = 0; kk < DK; kk++) {
            float4 a = *(const float4*)(qsT + kk * 68 + 4 * ty);
            float4 bb = *(const float4*)(ksT + kk * 68 + 4 * tx);
            acc[0][0] += a.x * bb.x; acc[0][1] += a.x * bb.y; acc[0][2] += a.x * bb.z; acc[0][3] += a.x * bb.w;
            acc[1][0] += a.y * bb.x; acc[1][1] += a.y * bb.y; acc[1][2] += a.y * bb.z; acc[1][3] += a.y * bb.w;
            acc[2][0] += a.z * bb.x; acc[2][1] += a.z * bb.y; acc[2][2] += a.z * bb.z; acc[2][3] += a.z * bb.w;
            acc[3][0] += a.w * bb.x; acc[3][1] += a.w * bb.y; acc[3][2] += a.w * bb.z; acc[3][3] += a.w * bb.w;
        }

        // --- RBF modulation + online softmax partial ---
#pragma unroll
        for (int i = 0; i < 4; i++) {
            float sv[4];
            float rm = -INF_F;
#pragma unroll
            for (int j = 0; j < 4; j++) {
                int c = 4 * tx + j;
                float dx = qcx[i] - mc[c * 3 + 0];
                float dy = qcy[i] - mc[c * 3 + 1];
                float dz = qcz[i] - mc[c * 3 + 2];
                float d2 = dx * dx + dy * dy + dz * dz;
                float s = acc[i][j];
                float arg = fmaxf(d2, s2) * inv2s2;           // in [0.5, 4.5] when unmasked
                float mod = s * __expf(copysignf(arg, -s));   // s<0 -> *exp(+arg), else *exp(-arg)
                bool masked = (kpf[c] != 0.f) || (d2 > nine_s2);
                sv[j] = masked ? -INF_F : mod;
                rm = fmaxf(rm, sv[j]);
            }
            // row max across 16 lanes
            rm = fmaxf(rm, __shfl_xor_sync(0xffffffffu, rm, 1));
            rm = fmaxf(rm, __shfl_xor_sync(0xffffffffu, rm, 2));
            rm = fmaxf(rm, __shfl_xor_sync(0xffffffffu, rm, 4));
            rm = fmaxf(rm, __shfl_xor_sync(0xffffffffu, rm, 8));
            float nm = fmaxf(mI[i], rm);
            float cf, psum = 0.f;
            if (nm == -INF_F) {          // fully masked so far
                cf = 1.f;
#pragma unroll
                for (int j = 0; j < 4; j++) sv[j] = 0.f;
            } else {
                cf = __expf(mI[i] - nm); // mI = -inf -> 0
#pragma unroll
                for (int j = 0; j < 4; j++) {
                    sv[j] = __expf(sv[j] - nm);   // -inf -> 0
                    psum += sv[j];
                }
            }
            psum += __shfl_xor_sync(0xffffffffu, psum, 1);
            psum += __shfl_xor_sync(0xffffffffu, psum, 2);
            psum += __shfl_xor_sync(0xffffffffu, psum, 4);
            psum += __shfl_xor_sync(0xffffffffu, psum, 8);
            lI[i] = lI[i] * cf + psum;
            mI[i] = nm;
#pragma unroll
            for (int j = 0; j < 4; j++) accO[i][j] *= cf;
            *(float4*)(ps + (4 * ty + i) * 68 + 4 * tx) = make_float4(sv[0], sv[1], sv[2], sv[3]);
        }
        __syncthreads();

        // --- O += P V ---
#pragma unroll 4
        for (int mm = 0; mm < 64; mm++) {
            float4 bv = *(const float4*)(vs + mm * 68 + 4 * tx);
            float a0 = ps[(4 * ty + 0) * 68 + mm];
            float a1 = ps[(4 * ty + 1) * 68 + mm];
            float a2 = ps[(4 * ty + 2) * 68 + mm];
            float a3 = ps[(4 * ty + 3) * 68 + mm];
            accO[0][0] += a0 * bv.x; accO[0][1] += a0 * bv.y; accO[0][2] += a0 * bv.z; accO[0][3] += a0 * bv.w;
            accO[1][0] += a1 * bv.x; accO[1][1] += a1 * bv.y; accO[1][2] += a1 * bv.z; accO[1][3] += a1 * bv.w;
            accO[2][0] += a2 * bv.x; accO[2][1] += a2 * bv.y; accO[2][2] += a2 * bv.z; accO[2][3] += a2 * bv.w;
            accO[3][0] += a3 * bv.x; accO[3][1] += a3 * bv.y; accO[3][2] += a3 * bv.z; accO[3][3] += a3 * bv.w;
        }
        __syncthreads();
    }

    // normalize + write [b][n][h*64+dk]
#pragma unroll
    for (int i = 0; i < 4; i++) {
        float inv = 1.0f / lI[i];
        float4 o = make_float4(accO[i][0] * inv, accO[i][1] * inv, accO[i][2] * inv, accO[i][3] * inv);
        *(float4*)(g_o + ((size_t)b * NTOK + q0 + 4 * ty + i) * DM + h * DK + 4 * tx) = o;
    }
}

// ---------------------------------------------------------------------------
// Output projection: Y[i][c] = sum_d O[i][d] * out_w[c][d] + out_b[c]
// ---------------------------------------------------------------------------
__global__ __launch_bounds__(256) void outproj_kernel(
    const float* __restrict__ ow, const float* __restrict__ ob, float* __restrict__ out)
{
    __shared__ float AsT[32 * 68];   // [kk][row]
    __shared__ float Bs [32 * 68];   // [kk][col]  (= out_w transposed)

    const int tid = threadIdx.x;
    const int tx = tid & 15, ty = tid >> 4;
    const int c0 = blockIdx.x * 64;
    const int r0 = blockIdx.y * 64;

    float acc[4][4];
#pragma unroll
    for (int i = 0; i < 4; i++)
#pragma unroll
        for (int j = 0; j < 4; j++) acc[i][j] = 0.f;

    for (int k0 = 0; k0 < DM; k0 += 32) {
        {
            int r = tid >> 2, j = tid & 3;
            const float4* asrc = (const float4*)(g_o + (size_t)(r0 + r) * DM + k0 + j * 8);
#pragma unroll
            for (int p = 0; p < 2; p++) {
                float4 a4 = asrc[p];
                int d = j * 8 + p * 4;
                AsT[(d + 0) * 68 + r] = a4.x;
                AsT[(d + 1) * 68 + r] = a4.y;
                AsT[(d + 2) * 68 + r] = a4.z;
                AsT[(d + 3) * 68 + r] = a4.w;
            }
        }
        {
            int cc = tid >> 2, j = tid & 3;
            const float4* bsrc = (const float4*)(ow + (size_t)(c0 + cc) * DM + k0 + j * 8);
#pragma unroll
            for (int p = 0; p < 2; p++) {
                float4 w4 = bsrc[p];
                int d = j * 8 + p * 4;
                Bs[(d + 0) * 68 + cc] = w4.x;
                Bs[(d + 1) * 68 + cc] = w4.y;
                Bs[(d + 2) * 68 + cc] = w4.z;
                Bs[(d + 3) * 68 + cc] = w4.w;
            }
        }
        __syncthreads();
#pragma unroll
        for (int kk = 0; kk < 32; kk++) {
            float4 a = *(const float4*)(AsT + kk * 68 + 4 * ty);
            float4 b = *(const float4*)(Bs  + kk * 68 + 4 * tx);
            acc[0][0] += a.x * b.x; acc[0][1] += a.x * b.y; acc[0][2] += a.x * b.z; acc[0][3] += a.x * b.w;
            acc[1][0] += a.y * b.x; acc[1][1] += a.y * b.y; acc[1][2] += a.y * b.z; acc[1][3] += a.y * b.w;
            acc[2][0] += a.z * b.x; acc[2][1] += a.z * b.y; acc[2][2] += a.z * b.z; acc[2][3] += a.z * b.w;
            acc[3][0] += a.w * b.x; acc[3][1] += a.w * b.y; acc[3][2] += a.w * b.z; acc[3][3] += a.w * b.w;
        }
        __syncthreads();
    }

    float4 bias = *(const float4*)(ob + c0 + 4 * tx);
#pragma unroll
    for (int i = 0; i < 4; i++) {
        int row = r0 + 4 * ty + i;
        float4 o = make_float4(acc[i][0] + bias.x, acc[i][1] + bias.y,
                               acc[i][2] + bias.z, acc[i][3] + bias.w);
        *(float4*)(out + (size_t)row * DM + c0 + 4 * tx) = o;
    }
}

// ---------------------------------------------------------------------------
extern "C" void kernel_launch(void* const* d_in, const int* in_sizes, int n_in,
                              void* d_out, int out_size)
{
    const float* q      = (const float*)d_in[0];
    const float* k      = (const float*)d_in[1];
    const float* v      = (const float*)d_in[2];
    const float* coords = (const float*)d_in[3];
    const unsigned char* kpm = (const unsigned char*)d_in[4];
    const float* qp     = (const float*)d_in[5];
    const float* kpj    = (const float*)d_in[6];
    const float* vp     = (const float*)d_in[7];
    const float* ow     = (const float*)d_in[8];
    const float* ob     = (const float*)d_in[9];
    float* out = (float*)d_out;

    const int attn_smem = 17664 * 4;   // 70656 B
    cudaFuncSetAttribute(attn_kernel, cudaFuncAttributeMaxDynamicSharedMemorySize, attn_smem);

    proj_kernel<<<dim3(8, 64, 3), 256>>>(q, k, v, qp, kpj, vp);
    attn_kernel<<<dim3(NTOK / 64, NH, B_SZ), 256, attn_smem>>>(coords, kpm);
    outproj_kernel<<<dim3(8, 64), 256>>>(ow, ob, out);
}

// round 5
// speedup vs baseline: 1.8512x; 1.8512x over previous
#include <cuda_runtime.h>
#include <cuda_bf16.h>
#include <math.h>
#include <cstdint>

#define B_SZ 2
#define NTOK 2048
#define NH 8
#define DK 64
#define DM 512
#define INF_F __int_as_float(0x7f800000)

// device scratch
__device__ float g_o[B_SZ * NTOK * DM];
__device__ __align__(16) __nv_bfloat16 g_qhi[B_SZ * NH * NTOK * DK];
__device__ __align__(16) __nv_bfloat16 g_qlo[B_SZ * NH * NTOK * DK];
__device__ __align__(16) __nv_bfloat16 g_khi[B_SZ * NH * NTOK * DK];
__device__ __align__(16) __nv_bfloat16 g_klo[B_SZ * NH * NTOK * DK];
__device__ __align__(16) __nv_bfloat16 g_vhi[B_SZ * NH * NTOK * DK];
__device__ __align__(16) __nv_bfloat16 g_vlo[B_SZ * NH * NTOK * DK];

// ---------------- helpers ----------------
__device__ __forceinline__ uint32_t smem_to_u32(const void* p) {
    uint32_t a;
    asm("{ .reg .u64 t; cvta.to.shared.u64 t, %1; cvt.u32.u64 %0, t; }" : "=r"(a) : "l"(p));
    return a;
}

#define LDMX2(r0, r1, addr) \
    asm volatile("ldmatrix.sync.aligned.m8n8.x2.shared.b16 {%0,%1}, [%2];" \
        : "=r"(r0), "=r"(r1) : "r"(addr))
#define LDMX2T(r0, r1, addr) \
    asm volatile("ldmatrix.sync.aligned.m8n8.x2.trans.shared.b16 {%0,%1}, [%2];" \
        : "=r"(r0), "=r"(r1) : "r"(addr))
#define LDMX4(r, addr) \
    asm volatile("ldmatrix.sync.aligned.m8n8.x4.shared.b16 {%0,%1,%2,%3}, [%4];" \
        : "=r"((r)[0]), "=r"((r)[1]), "=r"((r)[2]), "=r"((r)[3]) : "r"(addr))
#define MMA16816(d, a, b0, b1) \
    asm volatile("mma.sync.aligned.m16n8k16.row.col.f32.bf16.bf16.f32 " \
        "{%0,%1,%2,%3}, {%4,%5,%6,%7}, {%8,%9}, {%0,%1,%2,%3};" \
        : "+f"((d)[0]), "+f"((d)[1]), "+f"((d)[2]), "+f"((d)[3]) \
        : "r"((a)[0]), "r"((a)[1]), "r"((a)[2]), "r"((a)[3]), "r"(b0), "r"(b1))

// split-pack two floats -> bf16x2 hi (returned) and bf16x2 lo (out-param)
__device__ __forceinline__ uint32_t pack_split(float a, float b, uint32_t& lo) {
    __nv_bfloat162 hv = __float22bfloat162_rn(make_float2(a, b));
    float ra = a - __low2float(hv);
    float rb = b - __high2float(hv);
    __nv_bfloat162 lv = __float22bfloat162_rn(make_float2(ra, rb));
    lo = *reinterpret_cast<uint32_t*>(&lv);
    return *reinterpret_cast<uint32_t*>(&hv);
}

#define R1UP(acc, a, b) do { \
    acc[0][0]+=a.x*b.x; acc[0][1]+=a.x*b.y; acc[0][2]+=a.x*b.z; acc[0][3]+=a.x*b.w; \
    acc[1][0]+=a.y*b.x; acc[1][1]+=a.y*b.y; acc[1][2]+=a.y*b.z; acc[1][3]+=a.y*b.w; \
    acc[2][0]+=a.z*b.x; acc[2][1]+=a.z*b.y; acc[2][2]+=a.z*b.z; acc[2][3]+=a.z*b.w; \
    acc[3][0]+=a.w*b.x; acc[3][1]+=a.w*b.y; acc[3][2]+=a.w*b.z; acc[3][3]+=a.w*b.w; } while(0)

// ---------------- projection GEMM (SIMT; outputs bf16 hi/lo) ----------------
__global__ __launch_bounds__(256) void proj_kernel(
    const float* __restrict__ q, const float* __restrict__ k, const float* __restrict__ v,
    const float* __restrict__ qp, const float* __restrict__ kpj, const float* __restrict__ vp)
{
    __shared__ float AsT[32 * 68];
    __shared__ float Bs [32 * 68];
    const int tid = threadIdx.x;
    const int tx = tid & 15, ty = tid >> 4;
    const int h = blockIdx.x, r0 = blockIdx.y * 64, z = blockIdx.z;
    const float* X = (z == 0) ? q : (z == 1) ? k : v;
    const float* W = (z == 0) ? qp : (z == 1) ? kpj : vp;

    float acc[4][4];
#pragma unroll
    for (int i = 0; i < 4; i++)
#pragma unroll
        for (int j = 0; j < 4; j++) acc[i][j] = 0.f;

    for (int k0 = 0; k0 < DM; k0 += 32) {
        {
            int r = tid >> 2, j = tid & 3;
            const float4* asrc = (const float4*)(X + (size_t)(r0 + r) * DM + k0 + j * 8);
#pragma unroll
            for (int p = 0; p < 2; p++) {
                float4 a4 = asrc[p];
                int d = j * 8 + p * 4;
                AsT[(d+0)*68 + r] = a4.x; AsT[(d+1)*68 + r] = a4.y;
                AsT[(d+2)*68 + r] = a4.z; AsT[(d+3)*68 + r] = a4.w;
            }
        }
        {
            int kk = tid >> 3, jj = tid & 7;
            const float4* bsrc = (const float4*)(W + (size_t)h * DM * DK + (size_t)(k0 + kk) * DK + jj * 8);
            *(float4*)(Bs + kk * 68 + jj * 8)     = bsrc[0];
            *(float4*)(Bs + kk * 68 + jj * 8 + 4) = bsrc[1];
        }
        __syncthreads();
#pragma unroll
        for (int kk = 0; kk < 32; kk++) {
            float4 a = *(const float4*)(AsT + kk * 68 + 4 * ty);
            float4 b = *(const float4*)(Bs  + kk * 68 + 4 * tx);
            R1UP(acc, a, b);
        }
        __syncthreads();
    }
    const float scale = (z == 0) ? 0.125f : 1.0f;
    __nv_bfloat16* hd = (z == 0) ? g_qhi : (z == 1) ? g_khi : g_vhi;
    __nv_bfloat16* ld = (z == 0) ? g_qlo : (z == 1) ? g_klo : g_vlo;
#pragma unroll
    for (int i = 0; i < 4; i++) {
        int row = r0 + 4 * ty + i;
        int bb = row >> 11, n = row & (NTOK - 1);
        float v0 = acc[i][0]*scale, v1 = acc[i][1]*scale, v2 = acc[i][2]*scale, v3 = acc[i][3]*scale;
        uint32_t l01, l23;
        uint32_t h01 = pack_split(v0, v1, l01);
        uint32_t h23 = pack_split(v2, v3, l23);
        size_t base = (((size_t)bb * NH + h) * NTOK + n) * DK + 4 * tx;
        *(uint2*)(hd + base) = make_uint2(h01, h23);
        *(uint2*)(ld + base) = make_uint2(l01, l23);
    }
}

// ---------------- mma.sync flash attention ----------------
// smem: kh[0,8K) kl[8K,16K) vh[16K,24K) vl[24K,32K); Q staged over same 32K before loop
// mcs float4[64] at 32768 (x,y,z,|k|^2 + padmask*1e30)
__global__ __launch_bounds__(256, 1) void attn_mma_kernel(
    const float* __restrict__ coords, const unsigned char* __restrict__ kpm)
{
    __shared__ uint4 smv[2112];   // 33792 B
    char* sm = (char*)smv;
    uint32_t sb = smem_to_u32(sm);

    const int tid = threadIdx.x;
    const int lane = tid & 31;
    const int w = tid >> 5;
    const int b = blockIdx.z, h = blockIdx.y;
    const int q0 = blockIdx.x * 128;

    const float tpow   = 0.98f * (float)h / 7.0f;
    const float spread = 3.7f + (powf(20.0f, tpow) - 1.0f) * (16.3f / 19.0f);
    const float s2 = spread * spread;
    const float nine_s2 = 9.0f * s2;
    const float inv2s2 = 0.5f / s2;

    const size_t bh = ((size_t)b * NH + h) * NTOK;

    // stage Q tile (hi -> [0,16K), lo -> [16K,32K))
    {
        const __nv_bfloat16* qh_g = g_qhi + (bh + q0) * DK;
        const __nv_bfloat16* ql_g = g_qlo + (bh + q0) * DK;
#pragma unroll
        for (int t = 0; t < 4; t++) {
            int idx = tid + t * 256;
            int row = idx >> 3, c = idx & 7;
            uint32_t doff = (uint32_t)row * 128 + (((uint32_t)c * 16) ^ ((uint32_t)(row & 7) * 16));
            *(uint4*)(sm + doff)         = *(const uint4*)(qh_g + (size_t)row * DK + c * 8);
            *(uint4*)(sm + 16384 + doff) = *(const uint4*)(ql_g + (size_t)row * DK + c * 8);
        }
    }
    __syncthreads();

    // Q A-fragments (persistent)
    uint32_t aqh[4][4], aql[4][4];
    {
        int r = w * 16 + (lane & 15);
        uint32_t rx = (uint32_t)((r & 7) * 16);
#pragma unroll
        for (int ks = 0; ks < 4; ks++) {
            uint32_t cb = (uint32_t)(ks * 32 + (lane >> 4) * 16);
            uint32_t off = (uint32_t)r * 128 + (cb ^ rx);
            LDMX4(aqh[ks], sb + off);
            LDMX4(aql[ks], sb + 16384 + off);
        }
    }

    const int g = lane >> 2;
    const int cq = 2 * (lane & 3);
    const int qr0 = q0 + w * 16 + g;   // warp-local rows g and g+8
    float qx0, qy0, qz0, qx1, qy1, qz1, qq0, qq1;
    {
        const float* c0p = coords + ((size_t)b * NTOK + qr0) * 3;
        const float* c1p = c0p + 24;
        qx0 = c0p[0]; qy0 = c0p[1]; qz0 = c0p[2];
        qx1 = c1p[0]; qy1 = c1p[1]; qz1 = c1p[2];
        qq0 = qx0*qx0 + qy0*qy0 + qz0*qz0;
        qq1 = qx1*qx1 + qy1*qy1 + qz1*qz1;
    }

    float O[8][4];
#pragma unroll
    for (int i = 0; i < 8; i++) { O[i][0]=0.f; O[i][1]=0.f; O[i][2]=0.f; O[i][3]=0.f; }
    float mr0 = -INF_F, mr1 = -INF_F, lr0 = 0.f, lr1 = 0.f;

    const __nv_bfloat16* kh_g = g_khi + bh * DK;
    const __nv_bfloat16* kl_g = g_klo + bh * DK;
    const __nv_bfloat16* vh_g = g_vhi + bh * DK;
    const __nv_bfloat16* vl_g = g_vlo + bh * DK;
    float4* mcs = (float4*)(sm + 32768);

    const uint32_t l7 = (uint32_t)(lane & 7);
    const uint32_t kxor = l7 * 16;
    const uint32_t krow128 = l7 * 128;
    const uint32_t ssel = (uint32_t)(((lane >> 3) & 1) * 16);
    const uint32_t vrow = (uint32_t)(lane & 15);

    for (int mt = 0; mt < NTOK / 64; mt++) {
        const int m0k = mt * 64;
        __syncthreads();
        // stage K/V hi/lo tiles (swizzled uint4 copies)
#pragma unroll
        for (int t = 0; t < 2; t++) {
            int idx = tid + t * 256;
            int row = idx >> 3, c = idx & 7;
            uint32_t doff = (uint32_t)row * 128 + (((uint32_t)c * 16) ^ ((uint32_t)(row & 7) * 16));
            size_t goff = (size_t)(m0k + row) * DK + c * 8;
            *(uint4*)(sm + doff)         = *(const uint4*)(kh_g + goff);
            *(uint4*)(sm + 8192 + doff)  = *(const uint4*)(kl_g + goff);
            *(uint4*)(sm + 16384 + doff) = *(const uint4*)(vh_g + goff);
            *(uint4*)(sm + 24576 + doff) = *(const uint4*)(vl_g + goff);
        }
        if (tid < 64) {
            const float* cp = coords + ((size_t)b * NTOK + m0k + tid) * 3;
            float kx = cp[0], ky = cp[1], kz = cp[2];
            float kk = kx*kx + ky*ky + kz*kz;
            if (kpm[(size_t)b * NTOK + m0k + tid]) kk += 1e30f;
            mcs[tid] = make_float4(kx, ky, kz, kk);
        }
        __syncthreads();

        // ---- S = (Qhi+Qlo)(Khi+Klo)^T (drop lo*lo) ----
        float S[8][4];
#pragma unroll
        for (int i = 0; i < 8; i++) { S[i][0]=0.f; S[i][1]=0.f; S[i][2]=0.f; S[i][3]=0.f; }
#pragma unroll
        for (int ks = 0; ks < 4; ks++) {
            uint32_t cb = (((uint32_t)(ks * 32)) + ssel) ^ kxor;
#pragma unroll
            for (int nt = 0; nt < 8; nt++) {
                uint32_t off = (uint32_t)nt * 1024 + krow128 + cb;
                uint32_t b0, b1, c0, c1;
                LDMX2(b0, b1, sb + off);            // K hi
                LDMX2(c0, c1, sb + 8192 + off);     // K lo
                MMA16816(S[nt], aqh[ks], b0, b1);
                MMA16816(S[nt], aql[ks], b0, b1);
                MMA16816(S[nt], aqh[ks], c0, c1);
            }
        }

        // ---- epilogue pass A: RBF modulate + mask, rowmax ----
        float rm0 = -INF_F, rm1 = -INF_F;
#pragma unroll
        for (int nt = 0; nt < 8; nt++) {
            float4 k0 = mcs[nt * 8 + cq];
            float4 k1 = mcs[nt * 8 + cq + 1];
            {
                float d2 = qq0 + k0.w - 2.f * (qx0*k0.x + qy0*k0.y + qz0*k0.z);
                float s = S[nt][0];
                float v = s * __expf(copysignf(fmaxf(d2, s2) * inv2s2, -s));
                v = (d2 > nine_s2) ? -INF_F : v;
                S[nt][0] = v; rm0 = fmaxf(rm0, v);
            }
            {
                float d2 = qq0 + k1.w - 2.f * (qx0*k1.x + qy0*k1.y + qz0*k1.z);
                float s = S[nt][1];
                float v = s * __expf(copysignf(fmaxf(d2, s2) * inv2s2, -s));
                v = (d2 > nine_s2) ? -INF_F : v;
                S[nt][1] = v; rm0 = fmaxf(rm0, v);
            }
            {
                float d2 = qq1 + k0.w - 2.f * (qx1*k0.x + qy1*k0.y + qz1*k0.z);
                float s = S[nt][2];
                float v = s * __expf(copysignf(fmaxf(d2, s2) * inv2s2, -s));
                v = (d2 > nine_s2) ? -INF_F : v;
                S[nt][2] = v; rm1 = fmaxf(rm1, v);
            }
            {
                float d2 = qq1 + k1.w - 2.f * (qx1*k1.x + qy1*k1.y + qz1*k1.z);
                float s = S[nt][3];
                float v = s * __expf(copysignf(fmaxf(d2, s2) * inv2s2, -s));
                v = (d2 > nine_s2) ? -INF_F : v;
                S[nt][3] = v; rm1 = fmaxf(rm1, v);
            }
        }
        rm0 = fmaxf(rm0, __shfl_xor_sync(0xffffffffu, rm0, 1));
        rm0 = fmaxf(rm0, __shfl_xor_sync(0xffffffffu, rm0, 2));
        rm1 = fmaxf(rm1, __shfl_xor_sync(0xffffffffu, rm1, 1));
        rm1 = fmaxf(rm1, __shfl_xor_sync(0xffffffffu, rm1, 2));

        float nm0 = fmaxf(mr0, rm0), nm1 = fmaxf(mr1, rm1);
        bool dead0 = (nm0 == -INF_F), dead1 = (nm1 == -INF_F);
        float cf0 = dead0 ? 1.f : __expf(mr0 - nm0);
        float cf1 = dead1 ? 1.f : __expf(mr1 - nm1);
#pragma unroll
        for (int nt = 0; nt < 8; nt++) {
            O[nt][0] *= cf0; O[nt][1] *= cf0;
            O[nt][2] *= cf1; O[nt][3] *= cf1;
        }
        // ---- pass B: exp + rowsum; P kept in S regs ----
        float rs0 = 0.f, rs1 = 0.f;
#pragma unroll
        for (int nt = 0; nt < 8; nt++) {
            float p0 = dead0 ? 0.f : __expf(S[nt][0] - nm0);
            float p1 = dead0 ? 0.f : __expf(S[nt][1] - nm0);
            float p2 = dead1 ? 0.f : __expf(S[nt][2] - nm1);
            float p3 = dead1 ? 0.f : __expf(S[nt][3] - nm1);
            rs0 += p0 + p1; rs1 += p2 + p3;
            S[nt][0] = p0; S[nt][1] = p1; S[nt][2] = p2; S[nt][3] = p3;
        }
        rs0 += __shfl_xor_sync(0xffffffffu, rs0, 1);
        rs0 += __shfl_xor_sync(0xffffffffu, rs0, 2);
        rs1 += __shfl_xor_sync(0xffffffffu, rs1, 1);
        rs1 += __shfl_xor_sync(0xffffffffu, rs1, 2);
        lr0 = lr0 * cf0 + rs0; lr1 = lr1 * cf1 + rs1;
        mr0 = nm0; mr1 = nm1;

        // ---- P fragments (C layout == A layout identity) ----
        uint32_t ph[4][4], pl[4][4];
#pragma unroll
        for (int ks = 0; ks < 4; ks++) {
            int t0 = 2 * ks, t1 = t0 + 1;
            ph[ks][0] = pack_split(S[t0][0], S[t0][1], pl[ks][0]);
            ph[ks][1] = pack_split(S[t0][2], S[t0][3], pl[ks][1]);
            ph[ks][2] = pack_split(S[t1][0], S[t1][1], pl[ks][2]);
            ph[ks][3] = pack_split(S[t1][2], S[t1][3], pl[ks][3]);
        }

        // ---- O += P V  (Phi*Vhi + Plo*Vhi + Phi*Vlo) ----
#pragma unroll
        for (int ks = 0; ks < 4; ks++) {
            uint32_t roff = (uint32_t)(ks * 16 + vrow) * 128;
#pragma unroll
            for (int nt = 0; nt < 8; nt++) {
                uint32_t off = roff + (((uint32_t)nt * 16) ^ kxor);
                uint32_t b0, b1, c0, c1;
                LDMX2T(b0, b1, sb + 16384 + off);   // V hi
                LDMX2T(c0, c1, sb + 24576 + off);   // V lo
                MMA16816(O[nt], ph[ks], b0, b1);
                MMA16816(O[nt], pl[ks], b0, b1);
                MMA16816(O[nt], ph[ks], c0, c1);
            }
        }
    }

    // normalize + write
    float inv0 = 1.f / lr0, inv1 = 1.f / lr1;
    float* orow0 = g_o + ((size_t)b * NTOK + qr0) * DM + h * DK;
    float* orow1 = orow0 + 8 * DM;
#pragma unroll
    for (int nt = 0; nt < 8; nt++) {
        *(float2*)(orow0 + nt * 8 + cq) = make_float2(O[nt][0] * inv0, O[nt][1] * inv0);
        *(float2*)(orow1 + nt * 8 + cq) = make_float2(O[nt][2] * inv1, O[nt][3] * inv1);
    }
}

// ---------------- output projection (SIMT) ----------------
__global__ __launch_bounds__(256) void outproj_kernel(
    const float* __restrict__ ow, const float* __restrict__ ob, float* __restrict__ out)
{
    __shared__ float AsT[32 * 68];
    __shared__ float Bs [32 * 68];
    const int tid = threadIdx.x;
    const int tx = tid & 15, ty = tid >> 4;
    const int c0 = blockIdx.x * 64, r0 = blockIdx.y * 64;

    float acc[4][4];
#pragma unroll
    for (int i = 0; i < 4; i++)
#pragma unroll
        for (int j = 0; j < 4; j++) acc[i][j] = 0.f;

    for (int k0 = 0; k0 < DM; k0 += 32) {
        {
            int r = tid >> 2, j = tid & 3;
            const float4* asrc = (const float4*)(g_o + (size_t)(r0 + r) * DM + k0 + j * 8);
#pragma unroll
            for (int p = 0; p < 2; p++) {
                float4 a4 = asrc[p];
                int d = j * 8 + p * 4;
                AsT[(d+0)*68 + r] = a4.x; AsT[(d+1)*68 + r] = a4.y;
                AsT[(d+2)*68 + r] = a4.z; AsT[(d+3)*68 + r] = a4.w;
            }
        }
        {
            int cc = tid >> 2, j = tid & 3;
            const float4* bsrc = (const float4*)(ow + (size_t)(c0 + cc) * DM + k0 + j * 8);
#pragma unroll
            for (int p = 0; p < 2; p++) {
                float4 w4 = bsrc[p];
                int d = j * 8 + p * 4;
                Bs[(d+0)*68 + cc] = w4.x; Bs[(d+1)*68 + cc] = w4.y;
                Bs[(d+2)*68 + cc] = w4.z; Bs[(d+3)*68 + cc] = w4.w;
            }
        }
        __syncthreads();
#pragma unroll
        for (int kk = 0; kk < 32; kk++) {
            float4 a = *(const float4*)(AsT + kk * 68 + 4 * ty);
            float4 b = *(const float4*)(Bs  + kk * 68 + 4 * tx);
            R1UP(acc, a, b);
        }
        __syncthreads();
    }

    float4 bias = *(const float4*)(ob + c0 + 4 * tx);
#pragma unroll
    for (int i = 0; i < 4; i++) {
        int row = r0 + 4 * ty + i;
        float4 o = make_float4(acc[i][0] + bias.x, acc[i][1] + bias.y,
                               acc[i][2] + bias.z, acc[i][3] + bias.w);
        *(float4*)(out + (size_t)row * DM + c0 + 4 * tx) = o;
    }
}

// ---------------------------------------------------------------------------
extern "C" void kernel_launch(void* const* d_in, const int* in_sizes, int n_in,
                              void* d_out, int out_size)
{
    const float* q      = (const float*)d_in[0];
    const float* k      = (const float*)d_in[1];
    const float* v      = (const float*)d_in[2];
    const float* coords = (const float*)d_in[3];
    const unsigned char* kpm = (const unsigned char*)d_in[4];
    const float* qp     = (const float*)d_in[5];
    const float* kpj    = (const float*)d_in[6];
    const float* vp     = (const float*)d_in[7];
    const float* ow     = (const float*)d_in[8];
    const float* ob     = (const float*)d_in[9];
    float* out = (float*)d_out;

    proj_kernel<<<dim3(8, 64, 3), 256>>>(q, k, v, qp, kpj, vp);
    attn_mma_kernel<<<dim3(NTOK / 128, NH, B_SZ), 256>>>(coords, kpm);
    outproj_kernel<<<dim3(8, 64), 256>>>(ow, ob, out);
}

// round 7
// speedup vs baseline: 2.3104x; 1.2481x over previous
#include <cuda_runtime.h>
#include <cuda_bf16.h>
#include <math.h>
#include <cstdint>

#define B_SZ 2
#define NTOK 2048
#define NH 8
#define DK 64
#define DM 512
#define INF_F __int_as_float(0x7f800000)

// device scratch
__device__ float g_o[B_SZ * NTOK * DM];
__device__ __align__(16) __nv_bfloat16 g_qhi[B_SZ * NH * NTOK * DK];
__device__ __align__(16) __nv_bfloat16 g_qlo[B_SZ * NH * NTOK * DK];
__device__ __align__(16) __nv_bfloat16 g_khi[B_SZ * NH * NTOK * DK];
__device__ __align__(16) __nv_bfloat16 g_klo[B_SZ * NH * NTOK * DK];
__device__ __align__(16) __nv_bfloat16 g_vhi[B_SZ * NH * NTOK * DK];
__device__ __align__(16) __nv_bfloat16 g_vlo[B_SZ * NH * NTOK * DK];

// ---------------- helpers ----------------
__device__ __forceinline__ uint32_t smem_to_u32(const void* p) {
    uint32_t a;
    asm("{ .reg .u64 t; cvta.to.shared.u64 t, %1; cvt.u32.u64 %0, t; }" : "=r"(a) : "l"(p));
    return a;
}

#define LDMX2(r0, r1, addr) \
    asm volatile("ldmatrix.sync.aligned.m8n8.x2.shared.b16 {%0,%1}, [%2];" \
        : "=r"(r0), "=r"(r1) : "r"(addr))
#define LDMX2T(r0, r1, addr) \
    asm volatile("ldmatrix.sync.aligned.m8n8.x2.trans.shared.b16 {%0,%1}, [%2];" \
        : "=r"(r0), "=r"(r1) : "r"(addr))
#define LDMX4(r, addr) \
    asm volatile("ldmatrix.sync.aligned.m8n8.x4.shared.b16 {%0,%1,%2,%3}, [%4];" \
        : "=r"((r)[0]), "=r"((r)[1]), "=r"((r)[2]), "=r"((r)[3]) : "r"(addr))
#define MMA16816(d, a, b0, b1) \
    asm volatile("mma.sync.aligned.m16n8k16.row.col.f32.bf16.bf16.f32 " \
        "{%0,%1,%2,%3}, {%4,%5,%6,%7}, {%8,%9}, {%0,%1,%2,%3};" \
        : "+f"((d)[0]), "+f"((d)[1]), "+f"((d)[2]), "+f"((d)[3]) \
        : "r"((a)[0]), "r"((a)[1]), "r"((a)[2]), "r"((a)[3]), "r"(b0), "r"(b1))

__device__ __forceinline__ uint32_t pack_split(float a, float b, uint32_t& lo) {
    __nv_bfloat162 hv = __float22bfloat162_rn(make_float2(a, b));
    float ra = a - __low2float(hv);
    float rb = b - __high2float(hv);
    __nv_bfloat162 lv = __float22bfloat162_rn(make_float2(ra, rb));
    lo = *reinterpret_cast<uint32_t*>(&lv);
    return *reinterpret_cast<uint32_t*>(&hv);
}

// stage 8 consecutive floats as bf16 hi/lo uint4 pair
__device__ __forceinline__ void stage8(const float* __restrict__ src,
                                       char* hi_dst, char* lo_dst)
{
    float4 a = ((const float4*)src)[0];
    float4 b = ((const float4*)src)[1];
    uint32_t l0, l1, l2, l3;
    uint32_t h0 = pack_split(a.x, a.y, l0);
    uint32_t h1 = pack_split(a.z, a.w, l1);
    uint32_t h2 = pack_split(b.x, b.y, l2);
    uint32_t h3 = pack_split(b.z, b.w, l3);
    *(uint4*)hi_dst = make_uint4(h0, h1, h2, h3);
    *(uint4*)lo_dst = make_uint4(l0, l1, l2, l3);
}

// ============================================================
// proj: per head h: out[b,h,n,:] = X[b,n,:] @ W[h]; bf16 split output
// CTA: 128 rows x 64 cols (one head), K chunks of 32. 256 thr / 8 warps.
// ============================================================
__global__ __launch_bounds__(256) void proj_mma_kernel(
    const float* __restrict__ q, const float* __restrict__ k, const float* __restrict__ v,
    const float* __restrict__ qp, const float* __restrict__ kpj, const float* __restrict__ vp)
{
    __shared__ __align__(16) char sm[49152];  // AH 16K | AL 16K | BH 8K | BL 8K
    const uint32_t sb = smem_to_u32(sm);
    char* AH = sm;          char* AL = sm + 16384;
    char* BH = sm + 32768;  char* BL = sm + 40960;

    const int tid = threadIdx.x;
    const int lane = tid & 31, w = tid >> 5;
    const int h = blockIdx.x, r0 = blockIdx.y * 128, z = blockIdx.z;
    const float* X = (z == 0) ? q : (z == 1) ? k : v;
    const float* W = (z == 0) ? qp : (z == 1) ? kpj : vp;

    float acc[8][4];
#pragma unroll
    for (int i = 0; i < 8; i++) { acc[i][0]=0.f; acc[i][1]=0.f; acc[i][2]=0.f; acc[i][3]=0.f; }

    const uint32_t ssel = (uint32_t)(((lane >> 3) & 1) * 16);

    for (int k0 = 0; k0 < DM; k0 += 32) {
        // stage A: X[128 x 32] -> bf16 hi/lo, 128B padded swizzled rows
#pragma unroll
        for (int t = 0; t < 2; t++) {
            int p = tid + t * 256;
            int row = p >> 2, ch = p & 3;
            uint32_t off = (uint32_t)row * 128 + (((uint32_t)ch * 16) ^ ((uint32_t)(row & 7) * 16));
            stage8(X + (size_t)(r0 + row) * DM + k0 + ch * 8, AH + off, AL + off);
        }
        // stage B: W[h][32 k][64 n] -> transpose -> [n][k] rows
#pragma unroll
        for (int t = 0; t < 2; t++) {
            int p = tid + t * 256;
            int kk = p >> 4, n4 = (p & 15) * 4;
            float4 wv = *(const float4*)(W + (size_t)h * DM * DK + (size_t)(k0 + kk) * DK + n4);
            float vals[4] = {wv.x, wv.y, wv.z, wv.w};
#pragma unroll
            for (int e = 0; e < 4; e++) {
                int n = n4 + e;
                uint32_t off = (uint32_t)n * 128 + (((uint32_t)(kk * 2)) ^ ((uint32_t)(n & 7) * 16));
                __nv_bfloat16 hb = __float2bfloat16(vals[e]);
                __nv_bfloat16 lb = __float2bfloat16(vals[e] - __bfloat162float(hb));
                *(__nv_bfloat16*)(BH + off) = hb;
                *(__nv_bfloat16*)(BL + off) = lb;
            }
        }
        __syncthreads();

#pragma unroll
        for (int kb = 0; kb < 2; kb++) {
            int r = w * 16 + (lane & 15);
            uint32_t aoff = (uint32_t)r * 128 +
                (((uint32_t)(kb * 32 + ((lane >> 4) * 16))) ^ ((uint32_t)(r & 7) * 16));
            uint32_t ah[4], al[4];
            LDMX4(ah, sb + (uint32_t)(AH - sm) + aoff);
            LDMX4(al, sb + (uint32_t)(AL - sm) + aoff);
#pragma unroll
            for (int nt = 0; nt < 8; nt++) {
                int n = nt * 8 + (lane & 7);
                uint32_t boff = (uint32_t)n * 128 +
                    (((uint32_t)(kb * 32) + ssel) ^ ((uint32_t)(n & 7) * 16));
                uint32_t bh0, bh1, bl0, bl1;
                LDMX2(bh0, bh1, sb + (uint32_t)(BH - sm) + boff);
                LDMX2(bl0, bl1, sb + (uint32_t)(BL - sm) + boff);
                MMA16816(acc[nt], ah, bh0, bh1);
                MMA16816(acc[nt], al, bh0, bh1);
                MMA16816(acc[nt], ah, bl0, bl1);
            }
        }
        __syncthreads();
    }

    const float scale = (z == 0) ? 0.125f : 1.0f;
    __nv_bfloat16* hd = (z == 0) ? g_qhi : (z == 1) ? g_khi : g_vhi;
    __nv_bfloat16* ld = (z == 0) ? g_qlo : (z == 1) ? g_klo : g_vlo;
    const int gr0 = r0 + w * 16 + (lane >> 2);
    const int cq = 2 * (lane & 3);
#pragma unroll
    for (int rr = 0; rr < 2; rr++) {
        int gr = gr0 + rr * 8;
        int bb = gr >> 11, n = gr & (NTOK - 1);
        size_t base = (((size_t)bb * NH + h) * NTOK + n) * DK;
#pragma unroll
        for (int nt = 0; nt < 8; nt++) {
            float v0 = acc[nt][2 * rr] * scale, v1 = acc[nt][2 * rr + 1] * scale;
            uint32_t l01;
            uint32_t h01 = pack_split(v0, v1, l01);
            *(uint32_t*)(hd + base + nt * 8 + cq) = h01;
            *(uint32_t*)(ld + base + nt * 8 + cq) = l01;
        }
    }
}

// ============================================================
// mma.sync flash attention (unchanged from R4 — validated)
// ============================================================
__global__ __launch_bounds__(256, 1) void attn_mma_kernel(
    const float* __restrict__ coords, const unsigned char* __restrict__ kpm)
{
    __shared__ uint4 smv[2112];
    char* sm = (char*)smv;
    uint32_t sb = smem_to_u32(sm);

    const int tid = threadIdx.x;
    const int lane = tid & 31;
    const int w = tid >> 5;
    const int b = blockIdx.z, h = blockIdx.y;
    const int q0 = blockIdx.x * 128;

    const float tpow   = 0.98f * (float)h / 7.0f;
    const float spread = 3.7f + (powf(20.0f, tpow) - 1.0f) * (16.3f / 19.0f);
    const float s2 = spread * spread;
    const float nine_s2 = 9.0f * s2;
    const float inv2s2 = 0.5f / s2;

    const size_t bh = ((size_t)b * NH + h) * NTOK;

    {
        const __nv_bfloat16* qh_g = g_qhi + (bh + q0) * DK;
        const __nv_bfloat16* ql_g = g_qlo + (bh + q0) * DK;
#pragma unroll
        for (int t = 0; t < 4; t++) {
            int idx = tid + t * 256;
            int row = idx >> 3, c = idx & 7;
            uint32_t doff = (uint32_t)row * 128 + (((uint32_t)c * 16) ^ ((uint32_t)(row & 7) * 16));
            *(uint4*)(sm + doff)         = *(const uint4*)(qh_g + (size_t)row * DK + c * 8);
            *(uint4*)(sm + 16384 + doff) = *(const uint4*)(ql_g + (size_t)row * DK + c * 8);
        }
    }
    __syncthreads();

    uint32_t aqh[4][4], aql[4][4];
    {
        int r = w * 16 + (lane & 15);
        uint32_t rx = (uint32_t)((r & 7) * 16);
#pragma unroll
        for (int ks = 0; ks < 4; ks++) {
            uint32_t cb = (uint32_t)(ks * 32 + (lane >> 4) * 16);
            uint32_t off = (uint32_t)r * 128 + (cb ^ rx);
            LDMX4(aqh[ks], sb + off);
            LDMX4(aql[ks], sb + 16384 + off);
        }
    }

    const int g = lane >> 2;
    const int cq = 2 * (lane & 3);
    const int qr0 = q0 + w * 16 + g;
    float qx0, qy0, qz0, qx1, qy1, qz1, qq0, qq1;
    {
        const float* c0p = coords + ((size_t)b * NTOK + qr0) * 3;
        const float* c1p = c0p + 24;
        qx0 = c0p[0]; qy0 = c0p[1]; qz0 = c0p[2];
        qx1 = c1p[0]; qy1 = c1p[1]; qz1 = c1p[2];
        qq0 = qx0*qx0 + qy0*qy0 + qz0*qz0;
        qq1 = qx1*qx1 + qy1*qy1 + qz1*qz1;
    }

    float O[8][4];
#pragma unroll
    for (int i = 0; i < 8; i++) { O[i][0]=0.f; O[i][1]=0.f; O[i][2]=0.f; O[i][3]=0.f; }
    float mr0 = -INF_F, mr1 = -INF_F, lr0 = 0.f, lr1 = 0.f;

    const __nv_bfloat16* kh_g = g_khi + bh * DK;
    const __nv_bfloat16* kl_g = g_klo + bh * DK;
    const __nv_bfloat16* vh_g = g_vhi + bh * DK;
    const __nv_bfloat16* vl_g = g_vlo + bh * DK;
    float4* mcs = (float4*)(sm + 32768);

    const uint32_t l7 = (uint32_t)(lane & 7);
    const uint32_t kxor = l7 * 16;
    const uint32_t krow128 = l7 * 128;
    const uint32_t ssel = (uint32_t)(((lane >> 3) & 1) * 16);
    const uint32_t vrow = (uint32_t)(lane & 15);

    for (int mt = 0; mt < NTOK / 64; mt++) {
        const int m0k = mt * 64;
        __syncthreads();
#pragma unroll
        for (int t = 0; t < 2; t++) {
            int idx = tid + t * 256;
            int row = idx >> 3, c = idx & 7;
            uint32_t doff = (uint32_t)row * 128 + (((uint32_t)c * 16) ^ ((uint32_t)(row & 7) * 16));
            size_t goff = (size_t)(m0k + row) * DK + c * 8;
            *(uint4*)(sm + doff)         = *(const uint4*)(kh_g + goff);
            *(uint4*)(sm + 8192 + doff)  = *(const uint4*)(kl_g + goff);
            *(uint4*)(sm + 16384 + doff) = *(const uint4*)(vh_g + goff);
            *(uint4*)(sm + 24576 + doff) = *(const uint4*)(vl_g + goff);
        }
        if (tid < 64) {
            const float* cp = coords + ((size_t)b * NTOK + m0k + tid) * 3;
            float kx = cp[0], ky = cp[1], kz = cp[2];
            float kk = kx*kx + ky*ky + kz*kz;
            if (kpm[(size_t)b * NTOK + m0k + tid]) kk += 1e30f;
            mcs[tid] = make_float4(kx, ky, kz, kk);
        }
        __syncthreads();

        float S[8][4];
#pragma unroll
        for (int i = 0; i < 8; i++) { S[i][0]=0.f; S[i][1]=0.f; S[i][2]=0.f; S[i][3]=0.f; }
#pragma unroll
        for (int ks = 0; ks < 4; ks++) {
            uint32_t cb = (((uint32_t)(ks * 32)) + ssel) ^ kxor;
#pragma unroll
            for (int nt = 0; nt < 8; nt++) {
                uint32_t off = (uint32_t)nt * 1024 + krow128 + cb;
                uint32_t b0, b1, c0, c1;
                LDMX2(b0, b1, sb + off);
                LDMX2(c0, c1, sb + 8192 + off);
                MMA16816(S[nt], aqh[ks], b0, b1);
                MMA16816(S[nt], aql[ks], b0, b1);
                MMA16816(S[nt], aqh[ks], c0, c1);
            }
        }

        float rm0 = -INF_F, rm1 = -INF_F;
#pragma unroll
        for (int nt = 0; nt < 8; nt++) {
            float4 k0 = mcs[nt * 8 + cq];
            float4 k1 = mcs[nt * 8 + cq + 1];
            {
                float d2 = qq0 + k0.w - 2.f * (qx0*k0.x + qy0*k0.y + qz0*k0.z);
                float s = S[nt][0];
                float v = s * __expf(copysignf(fmaxf(d2, s2) * inv2s2, -s));
                v = (d2 > nine_s2) ? -INF_F : v;
                S[nt][0] = v; rm0 = fmaxf(rm0, v);
            }
            {
                float d2 = qq0 + k1.w - 2.f * (qx0*k1.x + qy0*k1.y + qz0*k1.z);
                float s = S[nt][1];
                float v = s * __expf(copysignf(fmaxf(d2, s2) * inv2s2, -s));
                v = (d2 > nine_s2) ? -INF_F : v;
                S[nt][1] = v; rm0 = fmaxf(rm0, v);
            }
            {
                float d2 = qq1 + k0.w - 2.f * (qx1*k0.x + qy1*k0.y + qz1*k0.z);
                float s = S[nt][2];
                float v = s * __expf(copysignf(fmaxf(d2, s2) * inv2s2, -s));
                v = (d2 > nine_s2) ? -INF_F : v;
                S[nt][2] = v; rm1 = fmaxf(rm1, v);
            }
            {
                float d2 = qq1 + k1.w - 2.f * (qx1*k1.x + qy1*k1.y + qz1*k1.z);
                float s = S[nt][3];
                float v = s * __expf(copysignf(fmaxf(d2, s2) * inv2s2, -s));
                v = (d2 > nine_s2) ? -INF_F : v;
                S[nt][3] = v; rm1 = fmaxf(rm1, v);
            }
        }
        rm0 = fmaxf(rm0, __shfl_xor_sync(0xffffffffu, rm0, 1));
        rm0 = fmaxf(rm0, __shfl_xor_sync(0xffffffffu, rm0, 2));
        rm1 = fmaxf(rm1, __shfl_xor_sync(0xffffffffu, rm1, 1));
        rm1 = fmaxf(rm1, __shfl_xor_sync(0xffffffffu, rm1, 2));

        float nm0 = fmaxf(mr0, rm0), nm1 = fmaxf(mr1, rm1);
        bool dead0 = (nm0 == -INF_F), dead1 = (nm1 == -INF_F);
        float cf0 = dead0 ? 1.f : __expf(mr0 - nm0);
        float cf1 = dead1 ? 1.f : __expf(mr1 - nm1);
#pragma unroll
        for (int nt = 0; nt < 8; nt++) {
            O[nt][0] *= cf0; O[nt][1] *= cf0;
            O[nt][2] *= cf1; O[nt][3] *= cf1;
        }
        float rs0 = 0.f, rs1 = 0.f;
#pragma unroll
        for (int nt = 0; nt < 8; nt++) {
            float p0 = dead0 ? 0.f : __expf(S[nt][0] - nm0);
            float p1 = dead0 ? 0.f : __expf(S[nt][1] - nm0);
            float p2 = dead1 ? 0.f : __expf(S[nt][2] - nm1);
            float p3 = dead1 ? 0.f : __expf(S[nt][3] - nm1);
            rs0 += p0 + p1; rs1 += p2 + p3;
            S[nt][0] = p0; S[nt][1] = p1; S[nt][2] = p2; S[nt][3] = p3;
        }
        rs0 += __shfl_xor_sync(0xffffffffu, rs0, 1);
        rs0 += __shfl_xor_sync(0xffffffffu, rs0, 2);
        rs1 += __shfl_xor_sync(0xffffffffu, rs1, 1);
        rs1 += __shfl_xor_sync(0xffffffffu, rs1, 2);
        lr0 = lr0 * cf0 + rs0; lr1 = lr1 * cf1 + rs1;
        mr0 = nm0; mr1 = nm1;

        uint32_t ph[4][4], pl[4][4];
#pragma unroll
        for (int ks = 0; ks < 4; ks++) {
            int t0 = 2 * ks, t1 = t0 + 1;
            ph[ks][0] = pack_split(S[t0][0], S[t0][1], pl[ks][0]);
            ph[ks][1] = pack_split(S[t0][2], S[t0][3], pl[ks][1]);
            ph[ks][2] = pack_split(S[t1][0], S[t1][1], pl[ks][2]);
            ph[ks][3] = pack_split(S[t1][2], S[t1][3], pl[ks][3]);
        }

#pragma unroll
        for (int ks = 0; ks < 4; ks++) {
            uint32_t roff = (uint32_t)(ks * 16 + vrow) * 128;
#pragma unroll
            for (int nt = 0; nt < 8; nt++) {
                uint32_t off = roff + (((uint32_t)nt * 16) ^ kxor);
                uint32_t b0, b1, c0, c1;
                LDMX2T(b0, b1, sb + 16384 + off);
                LDMX2T(c0, c1, sb + 24576 + off);
                MMA16816(O[nt], ph[ks], b0, b1);
                MMA16816(O[nt], pl[ks], b0, b1);
                MMA16816(O[nt], ph[ks], c0, c1);
            }
        }
    }

    float inv0 = 1.f / lr0, inv1 = 1.f / lr1;
    float* orow0 = g_o + ((size_t)b * NTOK + qr0) * DM + h * DK;
    float* orow1 = orow0 + 8 * DM;
#pragma unroll
    for (int nt = 0; nt < 8; nt++) {
        *(float2*)(orow0 + nt * 8 + cq) = make_float2(O[nt][0] * inv0, O[nt][1] * inv0);
        *(float2*)(orow1 + nt * 8 + cq) = make_float2(O[nt][2] * inv1, O[nt][3] * inv1);
    }
}

// ============================================================
// outproj: Y[i][c] = sum_d O[i][d] * ow[c][d] + ob[c]  (ow rows already [n][k])
// CTA: 128 rows x 64 cols; grid (8, 32)
// ============================================================
__global__ __launch_bounds__(256) void outproj_mma_kernel(
    const float* __restrict__ ow, const float* __restrict__ ob, float* __restrict__ out)
{
    __shared__ __align__(16) char sm[49152];
    const uint32_t sb = smem_to_u32(sm);
    char* AH = sm;          char* AL = sm + 16384;
    char* BH = sm + 32768;  char* BL = sm + 40960;

    const int tid = threadIdx.x;
    const int lane = tid & 31, w = tid >> 5;
    const int c0 = blockIdx.x * 64, r0 = blockIdx.y * 128;

    float acc[8][4];
#pragma unroll
    for (int i = 0; i < 8; i++) { acc[i][0]=0.f; acc[i][1]=0.f; acc[i][2]=0.f; acc[i][3]=0.f; }

    const uint32_t ssel = (uint32_t)(((lane >> 3) & 1) * 16);

    for (int k0 = 0; k0 < DM; k0 += 32) {
        // stage A: g_o[128 x 32]
#pragma unroll
        for (int t = 0; t < 2; t++) {
            int p = tid + t * 256;
            int row = p >> 2, ch = p & 3;
            uint32_t off = (uint32_t)row * 128 + (((uint32_t)ch * 16) ^ ((uint32_t)(row & 7) * 16));
            stage8(g_o + (size_t)(r0 + row) * DM + k0 + ch * 8, AH + off, AL + off);
        }
        // stage B: ow[(c0+row)][k0..k0+32) -> [n][k] rows (no transpose)
        {
            int p = tid;
            int row = p >> 2, ch = p & 3;
            uint32_t off = (uint32_t)row * 128 + (((uint32_t)ch * 16) ^ ((uint32_t)(row & 7) * 16));
            stage8(ow + (size_t)(c0 + row) * DM + k0 + ch * 8, BH + off, BL + off);
        }
        __syncthreads();

#pragma unroll
        for (int kb = 0; kb < 2; kb++) {
            int r = w * 16 + (lane & 15);
            uint32_t aoff = (uint32_t)r * 128 +
                (((uint32_t)(kb * 32 + ((lane >> 4) * 16))) ^ ((uint32_t)(r & 7) * 16));
            uint32_t ah[4], al[4];
            LDMX4(ah, sb + (uint32_t)(AH - sm) + aoff);
            LDMX4(al, sb + (uint32_t)(AL - sm) + aoff);
#pragma unroll
            for (int nt = 0; nt < 8; nt++) {
                int n = nt * 8 + (lane & 7);
                uint32_t boff = (uint32_t)n * 128 +
                    (((uint32_t)(kb * 32) + ssel) ^ ((uint32_t)(n & 7) * 16));
                uint32_t bh0, bh1, bl0, bl1;
                LDMX2(bh0, bh1, sb + (uint32_t)(BH - sm) + boff);
                LDMX2(bl0, bl1, sb + (uint32_t)(BL - sm) + boff);
                MMA16816(acc[nt], ah, bh0, bh1);
                MMA16816(acc[nt], al, bh0, bh1);
                MMA16816(acc[nt], ah, bl0, bl1);
            }
        }
        __syncthreads();
    }

    const int gr0 = r0 + w * 16 + (lane >> 2);
    const int cq = 2 * (lane & 3);
#pragma unroll
    for (int rr = 0; rr < 2; rr++) {
        int gr = gr0 + rr * 8;
        float* orow = out + (size_t)gr * DM + c0;
#pragma unroll
        for (int nt = 0; nt < 8; nt++) {
            int col = nt * 8 + cq;
            float2 bias = *(const float2*)(ob + c0 + col);
            *(float2*)(orow + col) = make_float2(acc[nt][2 * rr] + bias.x,
                                                 acc[nt][2 * rr + 1] + bias.y);
        }
    }
}

// ---------------------------------------------------------------------------
extern "C" void kernel_launch(void* const* d_in, const int* in_sizes, int n_in,
                              void* d_out, int out_size)
{
    const float* q      = (const float*)d_in[0];
    const float* k      = (const float*)d_in[1];
    const float* v      = (const float*)d_in[2];
    const float* coords = (const float*)d_in[3];
    const unsigned char* kpm = (const unsigned char*)d_in[4];
    const float* qp     = (const float*)d_in[5];
    const float* kpj    = (const float*)d_in[6];
    const float* vp     = (const float*)d_in[7];
    const float* ow     = (const float*)d_in[8];
    const float* ob     = (const float*)d_in[9];
    float* out = (float*)d_out;

    proj_mma_kernel<<<dim3(8, 32, 3), 256>>>(q, k, v, qp, kpj, vp);
    attn_mma_kernel<<<dim3(NTOK / 128, NH, B_SZ), 256>>>(coords, kpm);
    outproj_mma_kernel<<<dim3(8, 32), 256>>>(ow, ob, out);
}

// round 9
// speedup vs baseline: 2.8412x; 1.2298x over previous
#include <cuda_runtime.h>
#include <cuda_bf16.h>
#include <math.h>
#include <cstdint>

#define B_SZ 2
#define NTOK 2048
#define NH 8
#define DK 64
#define DM 512
#define INF_F __int_as_float(0x7f800000)

// device scratch
__device__ float g_o[B_SZ * NTOK * DM];
__device__ __align__(16) __nv_bfloat16 g_qhi[B_SZ * NH * NTOK * DK];
__device__ __align__(16) __nv_bfloat16 g_qlo[B_SZ * NH * NTOK * DK];
__device__ __align__(16) __nv_bfloat16 g_khi[B_SZ * NH * NTOK * DK];
__device__ __align__(16) __nv_bfloat16 g_klo[B_SZ * NH * NTOK * DK];
__device__ __align__(16) __nv_bfloat16 g_vhi[B_SZ * NH * NTOK * DK];
__device__ __align__(16) __nv_bfloat16 g_vlo[B_SZ * NH * NTOK * DK];
// pre-split inputs: [z][b][n][d]
__device__ __align__(16) __nv_bfloat16 g_xhi[3 * B_SZ * NTOK * DM];
__device__ __align__(16) __nv_bfloat16 g_xlo[3 * B_SZ * NTOK * DM];
// pre-split transposed weights: [z][h][n][k]
__device__ __align__(16) __nv_bfloat16 g_whi[3 * NH * DK * DM];
__device__ __align__(16) __nv_bfloat16 g_wlo[3 * NH * DK * DM];

// ---------------- helpers ----------------
__device__ __forceinline__ uint32_t smem_to_u32(const void* p) {
    uint32_t a;
    asm("{ .reg .u64 t; cvta.to.shared.u64 t, %1; cvt.u32.u64 %0, t; }" : "=r"(a) : "l"(p));
    return a;
}

#define LDMX2(r0, r1, addr) \
    asm volatile("ldmatrix.sync.aligned.m8n8.x2.shared.b16 {%0,%1}, [%2];" \
        : "=r"(r0), "=r"(r1) : "r"(addr))
#define LDMX2T(r0, r1, addr) \
    asm volatile("ldmatrix.sync.aligned.m8n8.x2.trans.shared.b16 {%0,%1}, [%2];" \
        : "=r"(r0), "=r"(r1) : "r"(addr))
#define LDMX4(r, addr) \
    asm volatile("ldmatrix.sync.aligned.m8n8.x4.shared.b16 {%0,%1,%2,%3}, [%4];" \
        : "=r"((r)[0]), "=r"((r)[1]), "=r"((r)[2]), "=r"((r)[3]) : "r"(addr))
#define MMA16816(d, a, b0, b1) \
    asm volatile("mma.sync.aligned.m16n8k16.row.col.f32.bf16.bf16.f32 " \
        "{%0,%1,%2,%3}, {%4,%5,%6,%7}, {%8,%9}, {%0,%1,%2,%3};" \
        : "+f"((d)[0]), "+f"((d)[1]), "+f"((d)[2]), "+f"((d)[3]) \
        : "r"((a)[0]), "r"((a)[1]), "r"((a)[2]), "r"((a)[3]), "r"(b0), "r"(b1))

#define CP_ASYNC16(dst, src) \
    asm volatile("cp.async.cg.shared.global [%0], [%1], 16;" :: "r"(dst), "l"(src) : "memory")
#define CP_COMMIT()  asm volatile("cp.async.commit_group;" ::: "memory")
#define CP_WAIT1()   asm volatile("cp.async.wait_group 1;" ::: "memory")
#define CP_WAIT0()   asm volatile("cp.async.wait_group 0;" ::: "memory")

__device__ __forceinline__ uint32_t pack_split(float a, float b, uint32_t& lo) {
    __nv_bfloat162 hv = __float22bfloat162_rn(make_float2(a, b));
    float ra = a - __low2float(hv);
    float rb = b - __high2float(hv);
    __nv_bfloat162 lv = __float22bfloat162_rn(make_float2(ra, rb));
    lo = *reinterpret_cast<uint32_t*>(&lv);
    return *reinterpret_cast<uint32_t*>(&hv);
}

__device__ __forceinline__ void stage8(const float* __restrict__ src,
                                       char* hi_dst, char* lo_dst)
{
    float4 a = ((const float4*)src)[0];
    float4 b = ((const float4*)src)[1];
    uint32_t l0, l1, l2, l3;
    uint32_t h0 = pack_split(a.x, a.y, l0);
    uint32_t h1 = pack_split(a.z, a.w, l1);
    uint32_t h2 = pack_split(b.x, b.y, l2);
    uint32_t h3 = pack_split(b.z, b.w, l3);
    *(uint4*)hi_dst = make_uint4(h0, h1, h2, h3);
    *(uint4*)lo_dst = make_uint4(l0, l1, l2, l3);
}

// ============================================================
// pre-split kernels
// ============================================================
__global__ __launch_bounds__(256) void presplit_x_kernel(
    const float* __restrict__ q, const float* __restrict__ k, const float* __restrict__ v)
{
    const int z = blockIdx.y;
    const float* X = (z == 0) ? q : (z == 1) ? k : v;
    size_t off = ((size_t)blockIdx.x * 256 + threadIdx.x) * 8;   // 1024 blocks cover 2M elems
    size_t base = (size_t)z * (B_SZ * NTOK * DM) + off;
    stage8(X + off, (char*)(g_xhi + base), (char*)(g_xlo + base));
}

__global__ __launch_bounds__(256) void presplit_w_kernel(
    const float* __restrict__ qp, const float* __restrict__ kpj, const float* __restrict__ vp)
{
    const int z = blockIdx.y;
    const float* W = (z == 0) ? qp : (z == 1) ? kpj : vp;
    int t = blockIdx.x * 256 + threadIdx.x;      // 128 blocks: 32768 groups of 8
    int kc = t & 63, n = (t >> 6) & 63, h = t >> 12;
    int k0 = kc * 8;
    float f[8];
#pragma unroll
    for (int e = 0; e < 8; e++)
        f[e] = W[(size_t)h * DM * DK + (size_t)(k0 + e) * DK + n];
    uint32_t hp[4], lp[4];
#pragma unroll
    for (int e = 0; e < 4; e++)
        hp[e] = pack_split(f[2*e], f[2*e+1], lp[e]);
    size_t base = (((size_t)z * NH + h) * DK + n) * DM + k0;
    *(uint4*)(g_whi + base) = make_uint4(hp[0], hp[1], hp[2], hp[3]);
    *(uint4*)(g_wlo + base) = make_uint4(lp[0], lp[1], lp[2], lp[3]);
}

// ============================================================
// proj v2: cp.async double-buffered, 128 rows x 128 cols (2 heads), K-chunk 64
// buffer layout (64KB): AH 16K | AL 16K | BH 16K | BL 16K; two buffers = 128KB
// ============================================================
#define PROJ_SMEM 131072
__global__ __launch_bounds__(256) void proj_mma_kernel()
{
    extern __shared__ __align__(16) char dsm[];
    const uint32_t sb = smem_to_u32(dsm);

    const int tid = threadIdx.x;
    const int lane = tid & 31, w = tid >> 5;
    const int hp = blockIdx.x;           // head pair
    const int r0 = blockIdx.y * 128;
    const int z  = blockIdx.z;

    const __nv_bfloat16* XH = g_xhi + (size_t)z * (B_SZ * NTOK * DM);
    const __nv_bfloat16* XL = g_xlo + (size_t)z * (B_SZ * NTOK * DM);
    const __nv_bfloat16* WH = g_whi + ((size_t)z * NH + hp * 2) * DK * DM;
    const __nv_bfloat16* WL = g_wlo + ((size_t)z * NH + hp * 2) * DK * DM;

    float acc[16][4];
#pragma unroll
    for (int i = 0; i < 16; i++) { acc[i][0]=0.f; acc[i][1]=0.f; acc[i][2]=0.f; acc[i][3]=0.f; }

    const uint32_t ssel = (uint32_t)(((lane >> 3) & 1) * 16);

    auto prefetch = [&](int c, int buf) {
        uint32_t base = sb + (uint32_t)buf * 65536;
#pragma unroll
        for (int t = 0; t < 4; t++) {
            int idx = tid + t * 256;            // 0..1023
            int row = idx >> 3, cc = idx & 7;
            uint32_t off = (uint32_t)row * 128 + (((uint32_t)cc * 16) ^ ((uint32_t)(row & 7) * 16));
            size_t xoff = (size_t)(r0 + row) * DM + c * 64 + cc * 8;
            size_t woff = (size_t)row * DM + c * 64 + cc * 8;
            CP_ASYNC16(base + off,         (const char*)(XH + xoff));
            CP_ASYNC16(base + 16384 + off, (const char*)(XL + xoff));
            CP_ASYNC16(base + 32768 + off, (const char*)(WH + woff));
            CP_ASYNC16(base + 49152 + off, (const char*)(WL + woff));
        }
    };

    prefetch(0, 0); CP_COMMIT();

    const int r = w * 16 + (lane & 15);
    const uint32_t rx = (uint32_t)((r & 7) * 16);

    for (int c = 0; c < 8; c++) {
        if (c + 1 < 8) { prefetch(c + 1, (c + 1) & 1); CP_COMMIT(); CP_WAIT1(); }
        else           { CP_WAIT0(); }
        __syncthreads();

        uint32_t base = sb + (uint32_t)(c & 1) * 65536;
#pragma unroll
        for (int kb = 0; kb < 4; kb++) {
            uint32_t aoff = (uint32_t)r * 128 +
                (((uint32_t)(kb * 32 + ((lane >> 4) * 16))) ^ rx);
            uint32_t ah[4], al[4];
            LDMX4(ah, base + aoff);
            LDMX4(al, base + 16384 + aoff);
#pragma unroll
            for (int nt = 0; nt < 16; nt++) {
                int n = nt * 8 + (lane & 7);
                uint32_t boff = (uint32_t)n * 128 +
                    (((uint32_t)(kb * 32) + ssel) ^ ((uint32_t)(n & 7) * 16));
                uint32_t bh0, bh1, bl0, bl1;
                LDMX2(bh0, bh1, base + 32768 + boff);
                LDMX2(bl0, bl1, base + 49152 + boff);
                MMA16816(acc[nt], ah, bh0, bh1);
                MMA16816(acc[nt], al, bh0, bh1);
                MMA16816(acc[nt], ah, bl0, bl1);
            }
        }
        __syncthreads();
    }

    const float scale = (z == 0) ? 0.125f : 1.0f;
    __nv_bfloat16* hd = (z == 0) ? g_qhi : (z == 1) ? g_khi : g_vhi;
    __nv_bfloat16* ld = (z == 0) ? g_qlo : (z == 1) ? g_klo : g_vlo;
    const int gr0 = r0 + w * 16 + (lane >> 2);
    const int cq = 2 * (lane & 3);
#pragma unroll
    for (int rr = 0; rr < 2; rr++) {
        int gr = gr0 + rr * 8;
        int bb = gr >> 11, n = gr & (NTOK - 1);
#pragma unroll
        for (int nt = 0; nt < 16; nt++) {
            int h = hp * 2 + (nt >> 3);
            int col = (nt & 7) * 8 + cq;
            size_t base = (((size_t)bb * NH + h) * NTOK + n) * DK + col;
            float v0 = acc[nt][2 * rr] * scale, v1 = acc[nt][2 * rr + 1] * scale;
            uint32_t l01;
            uint32_t h01 = pack_split(v0, v1, l01);
            *(uint32_t*)(hd + base) = h01;
            *(uint32_t*)(ld + base) = l01;
        }
    }
}

// ============================================================
// attention v2: cp.async double-buffered K/V/coords/kpm
// dynamic smem: buf[2] x 32KB (KH|KL|VH|VL 8K each) + [65536 + buf*1024]: coords 768B, kpm 64B
// ============================================================
#define ATTN_SMEM 67584
__global__ __launch_bounds__(256, 1) void attn_mma_kernel(
    const float* __restrict__ coords, const unsigned char* __restrict__ kpm)
{
    extern __shared__ __align__(16) char asm_sm[];
    char* sm = asm_sm;
    const uint32_t sb = smem_to_u32(sm);

    const int tid = threadIdx.x;
    const int lane = tid & 31;
    const int w = tid >> 5;
    const int b = blockIdx.z, h = blockIdx.y;
    const int q0 = blockIdx.x * 128;

    const float tpow   = 0.98f * (float)h / 7.0f;
    const float spread = 3.7f + (powf(20.0f, tpow) - 1.0f) * (16.3f / 19.0f);
    const float s2 = spread * spread;
    const float nine_s2 = 9.0f * s2;
    const float inv2s2 = 0.5f / s2;

    const size_t bh = ((size_t)b * NH + h) * NTOK;

    // stage Q into buf0 area (plain loads; once)
    {
        const __nv_bfloat16* qh_g = g_qhi + (bh + q0) * DK;
        const __nv_bfloat16* ql_g = g_qlo + (bh + q0) * DK;
#pragma unroll
        for (int t = 0; t < 4; t++) {
            int idx = tid + t * 256;
            int row = idx >> 3, c = idx & 7;
            uint32_t doff = (uint32_t)row * 128 + (((uint32_t)c * 16) ^ ((uint32_t)(row & 7) * 16));
            *(uint4*)(sm + doff)         = *(const uint4*)(qh_g + (size_t)row * DK + c * 8);
            *(uint4*)(sm + 16384 + doff) = *(const uint4*)(ql_g + (size_t)row * DK + c * 8);
        }
    }
    __syncthreads();

    uint32_t aqh[4][4], aql[4][4];
    {
        int r = w * 16 + (lane & 15);
        uint32_t rx = (uint32_t)((r & 7) * 16);
#pragma unroll
        for (int ks = 0; ks < 4; ks++) {
            uint32_t cb = (uint32_t)(ks * 32 + (lane >> 4) * 16);
            uint32_t off = (uint32_t)r * 128 + (cb ^ rx);
            LDMX4(aqh[ks], sb + off);
            LDMX4(aql[ks], sb + 16384 + off);
        }
    }
    __syncthreads();   // all Q frags extracted before buf0 is overwritten by prefetch

    const int g = lane >> 2;
    const int cq = 2 * (lane & 3);
    const int qr0 = q0 + w * 16 + g;
    float qx0, qy0, qz0, qx1, qy1, qz1;
    {
        const float* c0p = coords + ((size_t)b * NTOK + qr0) * 3;
        const float* c1p = c0p + 24;
        qx0 = c0p[0]; qy0 = c0p[1]; qz0 = c0p[2];
        qx1 = c1p[0]; qy1 = c1p[1]; qz1 = c1p[2];
    }

    float O[8][4];
#pragma unroll
    for (int i = 0; i < 8; i++) { O[i][0]=0.f; O[i][1]=0.f; O[i][2]=0.f; O[i][3]=0.f; }
    float mr0 = -INF_F, mr1 = -INF_F, lr0 = 0.f, lr1 = 0.f;

    const __nv_bfloat16* kh_g = g_khi + bh * DK;
    const __nv_bfloat16* kl_g = g_klo + bh * DK;
    const __nv_bfloat16* vh_g = g_vhi + bh * DK;
    const __nv_bfloat16* vl_g = g_vlo + bh * DK;

    auto prefetch = [&](int mtile, int buf) {
        uint32_t base = sb + (uint32_t)buf * 32768;
        int m0 = mtile * 64;
#pragma unroll
        for (int t = 0; t < 2; t++) {
            int idx = tid + t * 256;            // 0..511
            int row = idx >> 3, cc = idx & 7;
            uint32_t off = (uint32_t)row * 128 + (((uint32_t)cc * 16) ^ ((uint32_t)(row & 7) * 16));
            size_t goff = (size_t)(m0 + row) * DK + cc * 8;
            CP_ASYNC16(base + off,         (const char*)(kh_g + goff));
            CP_ASYNC16(base + 8192 + off,  (const char*)(kl_g + goff));
            CP_ASYNC16(base + 16384 + off, (const char*)(vh_g + goff));
            CP_ASYNC16(base + 24576 + off, (const char*)(vl_g + goff));
        }
        uint32_t cbase = sb + 65536 + (uint32_t)buf * 1024;
        if (tid < 48)
            CP_ASYNC16(cbase + tid * 16,
                       (const char*)coords + ((size_t)b * NTOK + m0) * 12 + tid * 16);
        else if (tid >= 64 && tid < 68)
            CP_ASYNC16(cbase + 768 + (tid - 64) * 16,
                       (const char*)(kpm + (size_t)b * NTOK + m0 + (tid - 64) * 16));
    };

    const uint32_t l7 = (uint32_t)(lane & 7);
    const uint32_t kxor = l7 * 16;
    const uint32_t krow128 = l7 * 128;
    const uint32_t ssel = (uint32_t)(((lane >> 3) & 1) * 16);
    const uint32_t vrow = (uint32_t)(lane & 15);

    prefetch(0, 0); CP_COMMIT();

    for (int mt = 0; mt < NTOK / 64; mt++) {
        if (mt + 1 < NTOK / 64) { prefetch(mt + 1, (mt + 1) & 1); CP_COMMIT(); CP_WAIT1(); }
        else                    { CP_WAIT0(); }
        __syncthreads();

        const uint32_t base = sb + (uint32_t)(mt & 1) * 32768;
        const float* mc = (const float*)(sm + 65536 + (size_t)(mt & 1) * 1024);
        const unsigned char* kpms = (const unsigned char*)(sm + 65536 + (size_t)(mt & 1) * 1024 + 768);

        // ---- S ----
        float S[8][4];
#pragma unroll
        for (int i = 0; i < 8; i++) { S[i][0]=0.f; S[i][1]=0.f; S[i][2]=0.f; S[i][3]=0.f; }
#pragma unroll
        for (int ks = 0; ks < 4; ks++) {
            uint32_t cb = (((uint32_t)(ks * 32)) + ssel) ^ kxor;
#pragma unroll
            for (int nt = 0; nt < 8; nt++) {
                uint32_t off = (uint32_t)nt * 1024 + krow128 + cb;
                uint32_t b0, b1, c0, c1;
                LDMX2(b0, b1, base + off);
                LDMX2(c0, c1, base + 8192 + off);
                MMA16816(S[nt], aqh[ks], b0, b1);
                MMA16816(S[nt], aql[ks], b0, b1);
                MMA16816(S[nt], aqh[ks], c0, c1);
            }
        }

        // ---- epilogue pass A ----
        float rm0 = -INF_F, rm1 = -INF_F;
#pragma unroll
        for (int nt = 0; nt < 8; nt++) {
            int m0c = nt * 8 + cq;
            float k0x = mc[m0c*3+0], k0y = mc[m0c*3+1], k0z = mc[m0c*3+2];
            float k1x = mc[m0c*3+3], k1y = mc[m0c*3+4], k1z = mc[m0c*3+5];
            bool p0 = kpms[m0c] != 0, p1 = kpms[m0c+1] != 0;
            {
                float dx=qx0-k0x, dy=qy0-k0y, dz=qz0-k0z;
                float d2 = dx*dx+dy*dy+dz*dz;
                float s = S[nt][0];
                float v = s * __expf(copysignf(fmaxf(d2, s2)*inv2s2, -s));
                v = (d2 > nine_s2 || p0) ? -INF_F : v;
                S[nt][0]=v; rm0=fmaxf(rm0,v);
            }
            {
                float dx=qx0-k1x, dy=qy0-k1y, dz=qz0-k1z;
                float d2 = dx*dx+dy*dy+dz*dz;
                float s = S[nt][1];
                float v = s * __expf(copysignf(fmaxf(d2, s2)*inv2s2, -s));
                v = (d2 > nine_s2 || p1) ? -INF_F : v;
                S[nt][1]=v; rm0=fmaxf(rm0,v);
            }
            {
                float dx=qx1-k0x, dy=qy1-k0y, dz=qz1-k0z;
                float d2 = dx*dx+dy*dy+dz*dz;
                float s = S[nt][2];
                float v = s * __expf(copysignf(fmaxf(d2, s2)*inv2s2, -s));
                v = (d2 > nine_s2 || p0) ? -INF_F : v;
                S[nt][2]=v; rm1=fmaxf(rm1,v);
            }
            {
                float dx=qx1-k1x, dy=qy1-k1y, dz=qz1-k1z;
                float d2 = dx*dx+dy*dy+dz*dz;
                float s = S[nt][3];
                float v = s * __expf(copysignf(fmaxf(d2, s2)*inv2s2, -s));
                v = (d2 > nine_s2 || p1) ? -INF_F : v;
                S[nt][3]=v; rm1=fmaxf(rm1,v);
            }
        }
        rm0 = fmaxf(rm0, __shfl_xor_sync(0xffffffffu, rm0, 1));
        rm0 = fmaxf(rm0, __shfl_xor_sync(0xffffffffu, rm0, 2));
        rm1 = fmaxf(rm1, __shfl_xor_sync(0xffffffffu, rm1, 1));
        rm1 = fmaxf(rm1, __shfl_xor_sync(0xffffffffu, rm1, 2));

        float nm0 = fmaxf(mr0, rm0), nm1 = fmaxf(mr1, rm1);
        bool dead0 = (nm0 == -INF_F), dead1 = (nm1 == -INF_F);
        float cf0 = dead0 ? 1.f : __expf(mr0 - nm0);
        float cf1 = dead1 ? 1.f : __expf(mr1 - nm1);
#pragma unroll
        for (int nt = 0; nt < 8; nt++) {
            O[nt][0] *= cf0; O[nt][1] *= cf0;
            O[nt][2] *= cf1; O[nt][3] *= cf1;
        }
        float rs0 = 0.f, rs1 = 0.f;
#pragma unroll
        for (int nt = 0; nt < 8; nt++) {
            float p0 = dead0 ? 0.f : __expf(S[nt][0] - nm0);
            float p1 = dead0 ? 0.f : __expf(S[nt][1] - nm0);
            float p2 = dead1 ? 0.f : __expf(S[nt][2] - nm1);
            float p3 = dead1 ? 0.f : __expf(S[nt][3] - nm1);
            rs0 += p0 + p1; rs1 += p2 + p3;
            S[nt][0] = p0; S[nt][1] = p1; S[nt][2] = p2; S[nt][3] = p3;
        }
        rs0 += __shfl_xor_sync(0xffffffffu, rs0, 1);
        rs0 += __shfl_xor_sync(0xffffffffu, rs0, 2);
        rs1 += __shfl_xor_sync(0xffffffffu, rs1, 1);
        rs1 += __shfl_xor_sync(0xffffffffu, rs1, 2);
        lr0 = lr0 * cf0 + rs0; lr1 = lr1 * cf1 + rs1;
        mr0 = nm0; mr1 = nm1;

        uint32_t ph[4][4], pl[4][4];
#pragma unroll
        for (int ks = 0; ks < 4; ks++) {
            int t0 = 2 * ks, t1 = t0 + 1;
            ph[ks][0] = pack_split(S[t0][0], S[t0][1], pl[ks][0]);
            ph[ks][1] = pack_split(S[t0][2], S[t0][3], pl[ks][1]);
            ph[ks][2] = pack_split(S[t1][0], S[t1][1], pl[ks][2]);
            ph[ks][3] = pack_split(S[t1][2], S[t1][3], pl[ks][3]);
        }

        // ---- O += P V ----
#pragma unroll
        for (int ks = 0; ks < 4; ks++) {
            uint32_t roff = (uint32_t)(ks * 16 + vrow) * 128;
#pragma unroll
            for (int nt = 0; nt < 8; nt++) {
                uint32_t off = roff + (((uint32_t)nt * 16) ^ kxor);
                uint32_t b0, b1, c0, c1;
                LDMX2T(b0, b1, base + 16384 + off);
                LDMX2T(c0, c1, base + 24576 + off);
                MMA16816(O[nt], ph[ks], b0, b1);
                MMA16816(O[nt], pl[ks], b0, b1);
                MMA16816(O[nt], ph[ks], c0, c1);
            }
        }
        __syncthreads();
    }

    float inv0 = 1.f / lr0, inv1 = 1.f / lr1;
    float* orow0 = g_o + ((size_t)b * NTOK + qr0) * DM + h * DK;
    float* orow1 = orow0 + 8 * DM;
#pragma unroll
    for (int nt = 0; nt < 8; nt++) {
        *(float2*)(orow0 + nt * 8 + cq) = make_float2(O[nt][0] * inv0, O[nt][1] * inv0);
        *(float2*)(orow1 + nt * 8 + cq) = make_float2(O[nt][2] * inv1, O[nt][3] * inv1);
    }
}

// ============================================================
// outproj (R6, proven)
// ============================================================
__global__ __launch_bounds__(256) void outproj_mma_kernel(
    const float* __restrict__ ow, const float* __restrict__ ob, float* __restrict__ out)
{
    __shared__ __align__(16) char sm[49152];
    const uint32_t sb = smem_to_u32(sm);
    char* AH = sm;          char* AL = sm + 16384;
    char* BH = sm + 32768;  char* BL = sm + 40960;

    const int tid = threadIdx.x;
    const int lane = tid & 31, w = tid >> 5;
    const int c0 = blockIdx.x * 64, r0 = blockIdx.y * 128;

    float acc[8][4];
#pragma unroll
    for (int i = 0; i < 8; i++) { acc[i][0]=0.f; acc[i][1]=0.f; acc[i][2]=0.f; acc[i][3]=0.f; }

    const uint32_t ssel = (uint32_t)(((lane >> 3) & 1) * 16);

    for (int k0 = 0; k0 < DM; k0 += 32) {
#pragma unroll
        for (int t = 0; t < 2; t++) {
            int p = tid + t * 256;
            int row = p >> 2, ch = p & 3;
            uint32_t off = (uint32_t)row * 128 + (((uint32_t)ch * 16) ^ ((uint32_t)(row & 7) * 16));
            stage8(g_o + (size_t)(r0 + row) * DM + k0 + ch * 8, AH + off, AL + off);
        }
        {
            int p = tid;
            int row = p >> 2, ch = p & 3;
            uint32_t off = (uint32_t)row * 128 + (((uint32_t)ch * 16) ^ ((uint32_t)(row & 7) * 16));
            stage8(ow + (size_t)(c0 + row) * DM + k0 + ch * 8, BH + off, BL + off);
        }
        __syncthreads();

#pragma unroll
        for (int kb = 0; kb < 2; kb++) {
            int r = w * 16 + (lane & 15);
            uint32_t aoff = (uint32_t)r * 128 +
                (((uint32_t)(kb * 32 + ((lane >> 4) * 16))) ^ ((uint32_t)(r & 7) * 16));
            uint32_t ah[4], al[4];
            LDMX4(ah, sb + (uint32_t)(AH - sm) + aoff);
            LDMX4(al, sb + (uint32_t)(AL - sm) + aoff);
#pragma unroll
            for (int nt = 0; nt < 8; nt++) {
                int n = nt * 8 + (lane & 7);
                uint32_t boff = (uint32_t)n * 128 +
                    (((uint32_t)(kb * 32) + ssel) ^ ((uint32_t)(n & 7) * 16));
                uint32_t bh0, bh1, bl0, bl1;
                LDMX2(bh0, bh1, sb + (uint32_t)(BH - sm) + boff);
                LDMX2(bl0, bl1, sb + (uint32_t)(BL - sm) + boff);
                MMA16816(acc[nt], ah, bh0, bh1);
                MMA16816(acc[nt], al, bh0, bh1);
                MMA16816(acc[nt], ah, bl0, bl1);
            }
        }
        __syncthreads();
    }

    const int gr0 = r0 + w * 16 + (lane >> 2);
    const int cq = 2 * (lane & 3);
#pragma unroll
    for (int rr = 0; rr < 2; rr++) {
        int gr = gr0 + rr * 8;
        float* orow = out + (size_t)gr * DM + c0;
#pragma unroll
        for (int nt = 0; nt < 8; nt++) {
            int col = nt * 8 + cq;
            float2 bias = *(const float2*)(ob + c0 + col);
            *(float2*)(orow + col) = make_float2(acc[nt][2 * rr] + bias.x,
                                                 acc[nt][2 * rr + 1] + bias.y);
        }
    }
}

// ---------------------------------------------------------------------------
extern "C" void kernel_launch(void* const* d_in, const int* in_sizes, int n_in,
                              void* d_out, int out_size)
{
    const float* q      = (const float*)d_in[0];
    const float* k      = (const float*)d_in[1];
    const float* v      = (const float*)d_in[2];
    const float* coords = (const float*)d_in[3];
    const unsigned char* kpm = (const unsigned char*)d_in[4];
    const float* qp     = (const float*)d_in[5];
    const float* kpj    = (const float*)d_in[6];
    const float* vp     = (const float*)d_in[7];
    const float* ow     = (const float*)d_in[8];
    const float* ob     = (const float*)d_in[9];
    float* out = (float*)d_out;

    static int attr_set = 0;
    if (!attr_set) {
        cudaFuncSetAttribute(proj_mma_kernel, cudaFuncAttributeMaxDynamicSharedMemorySize, PROJ_SMEM);
        cudaFuncSetAttribute(attn_mma_kernel, cudaFuncAttributeMaxDynamicSharedMemorySize, ATTN_SMEM);
        attr_set = 1;
    }

    presplit_x_kernel<<<dim3(1024, 3), 256>>>(q, k, v);
    presplit_w_kernel<<<dim3(128, 3), 256>>>(qp, kpj, vp);
    proj_mma_kernel<<<dim3(4, 32, 3), 256, PROJ_SMEM>>>();
    attn_mma_kernel<<<dim3(NTOK / 128, NH, B_SZ), 256, ATTN_SMEM>>>(coords, kpm);
    outproj_mma_kernel<<<dim3(8, 32), 256>>>(ow, ob, out);
}

// round 10
// speedup vs baseline: 2.9129x; 1.0252x over previous
#include <cuda_runtime.h>
#include <cuda_bf16.h>
#include <math.h>
#include <cstdint>

#define B_SZ 2
#define NTOK 2048
#define NH 8
#define DK 64
#define DM 512
#define INF_F __int_as_float(0x7f800000)

// device scratch
__device__ float g_o[B_SZ * NTOK * DM];
__device__ __align__(16) __nv_bfloat16 g_qhi[B_SZ * NH * NTOK * DK];
__device__ __align__(16) __nv_bfloat16 g_qlo[B_SZ * NH * NTOK * DK];
__device__ __align__(16) __nv_bfloat16 g_khi[B_SZ * NH * NTOK * DK];
__device__ __align__(16) __nv_bfloat16 g_klo[B_SZ * NH * NTOK * DK];
__device__ __align__(16) __nv_bfloat16 g_vhi[B_SZ * NH * NTOK * DK];
__device__ __align__(16) __nv_bfloat16 g_vlo[B_SZ * NH * NTOK * DK];
// pre-split inputs: [z][b][n][d]
__device__ __align__(16) __nv_bfloat16 g_xhi[3 * B_SZ * NTOK * DM];
__device__ __align__(16) __nv_bfloat16 g_xlo[3 * B_SZ * NTOK * DM];
// pre-split transposed weights: [z][h][n][k]
__device__ __align__(16) __nv_bfloat16 g_whi[3 * NH * DK * DM];
__device__ __align__(16) __nv_bfloat16 g_wlo[3 * NH * DK * DM];

// ---------------- helpers ----------------
__device__ __forceinline__ uint32_t smem_to_u32(const void* p) {
    uint32_t a;
    asm("{ .reg .u64 t; cvta.to.shared.u64 t, %1; cvt.u32.u64 %0, t; }" : "=r"(a) : "l"(p));
    return a;
}

#define LDMX2(r0, r1, addr) \
    asm volatile("ldmatrix.sync.aligned.m8n8.x2.shared.b16 {%0,%1}, [%2];" \
        : "=r"(r0), "=r"(r1) : "r"(addr))
#define LDMX4(r, addr) \
    asm volatile("ldmatrix.sync.aligned.m8n8.x4.shared.b16 {%0,%1,%2,%3}, [%4];" \
        : "=r"((r)[0]), "=r"((r)[1]), "=r"((r)[2]), "=r"((r)[3]) : "r"(addr))
#define LDMX4T(r, addr) \
    asm volatile("ldmatrix.sync.aligned.m8n8.x4.trans.shared.b16 {%0,%1,%2,%3}, [%4];" \
        : "=r"((r)[0]), "=r"((r)[1]), "=r"((r)[2]), "=r"((r)[3]) : "r"(addr))
#define MMA16816(d, a, b0, b1) \
    asm volatile("mma.sync.aligned.m16n8k16.row.col.f32.bf16.bf16.f32 " \
        "{%0,%1,%2,%3}, {%4,%5,%6,%7}, {%8,%9}, {%0,%1,%2,%3};" \
        : "+f"((d)[0]), "+f"((d)[1]), "+f"((d)[2]), "+f"((d)[3]) \
        : "r"((a)[0]), "r"((a)[1]), "r"((a)[2]), "r"((a)[3]), "r"(b0), "r"(b1))

#define CP_ASYNC16(dst, src) \
    asm volatile("cp.async.cg.shared.global [%0], [%1], 16;" :: "r"(dst), "l"(src) : "memory")
#define CP_COMMIT()  asm volatile("cp.async.commit_group;" ::: "memory")
#define CP_WAIT1()   asm volatile("cp.async.wait_group 1;" ::: "memory")
#define CP_WAIT0()   asm volatile("cp.async.wait_group 0;" ::: "memory")

__device__ __forceinline__ uint32_t pack_split(float a, float b, uint32_t& lo) {
    __nv_bfloat162 hv = __float22bfloat162_rn(make_float2(a, b));
    float ra = a - __low2float(hv);
    float rb = b - __high2float(hv);
    __nv_bfloat162 lv = __float22bfloat162_rn(make_float2(ra, rb));
    lo = *reinterpret_cast<uint32_t*>(&lv);
    return *reinterpret_cast<uint32_t*>(&hv);
}

__device__ __forceinline__ void stage8(const float* __restrict__ src,
                                       char* hi_dst, char* lo_dst)
{
    float4 a = ((const float4*)src)[0];
    float4 b = ((const float4*)src)[1];
    uint32_t l0, l1, l2, l3;
    uint32_t h0 = pack_split(a.x, a.y, l0);
    uint32_t h1 = pack_split(a.z, a.w, l1);
    uint32_t h2 = pack_split(b.x, b.y, l2);
    uint32_t h3 = pack_split(b.z, b.w, l3);
    *(uint4*)hi_dst = make_uint4(h0, h1, h2, h3);
    *(uint4*)lo_dst = make_uint4(l0, l1, l2, l3);
}

// ============================================================
// pre-split kernels
// ============================================================
__global__ __launch_bounds__(256) void presplit_x_kernel(
    const float* __restrict__ q, const float* __restrict__ k, const float* __restrict__ v)
{
    const int z = blockIdx.y;
    const float* X = (z == 0) ? q : (z == 1) ? k : v;
    size_t off = ((size_t)blockIdx.x * 256 + threadIdx.x) * 8;
    size_t base = (size_t)z * (B_SZ * NTOK * DM) + off;
    stage8(X + off, (char*)(g_xhi + base), (char*)(g_xlo + base));
}

__global__ __launch_bounds__(256) void presplit_w_kernel(
    const float* __restrict__ qp, const float* __restrict__ kpj, const float* __restrict__ vp)
{
    const int z = blockIdx.y;
    const float* W = (z == 0) ? qp : (z == 1) ? kpj : vp;
    int t = blockIdx.x * 256 + threadIdx.x;
    int kc = t & 63, n = (t >> 6) & 63, h = t >> 12;
    int k0 = kc * 8;
    float f[8];
#pragma unroll
    for (int e = 0; e < 8; e++)
        f[e] = W[(size_t)h * DM * DK + (size_t)(k0 + e) * DK + n];
    uint32_t hp[4], lp[4];
#pragma unroll
    for (int e = 0; e < 4; e++)
        hp[e] = pack_split(f[2*e], f[2*e+1], lp[e]);
    size_t base = (((size_t)z * NH + h) * DK + n) * DM + k0;
    *(uint4*)(g_whi + base) = make_uint4(hp[0], hp[1], hp[2], hp[3]);
    *(uint4*)(g_wlo + base) = make_uint4(lp[0], lp[1], lp[2], lp[3]);
}

// ============================================================
// proj v2 (R8, proven): cp.async double-buffered
// ============================================================
#define PROJ_SMEM 131072
__global__ __launch_bounds__(256) void proj_mma_kernel()
{
    extern __shared__ __align__(16) char dsm[];
    const uint32_t sb = smem_to_u32(dsm);

    const int tid = threadIdx.x;
    const int lane = tid & 31, w = tid >> 5;
    const int hp = blockIdx.x;
    const int r0 = blockIdx.y * 128;
    const int z  = blockIdx.z;

    const __nv_bfloat16* XH = g_xhi + (size_t)z * (B_SZ * NTOK * DM);
    const __nv_bfloat16* XL = g_xlo + (size_t)z * (B_SZ * NTOK * DM);
    const __nv_bfloat16* WH = g_whi + ((size_t)z * NH + hp * 2) * DK * DM;
    const __nv_bfloat16* WL = g_wlo + ((size_t)z * NH + hp * 2) * DK * DM;

    float acc[16][4];
#pragma unroll
    for (int i = 0; i < 16; i++) { acc[i][0]=0.f; acc[i][1]=0.f; acc[i][2]=0.f; acc[i][3]=0.f; }

    const uint32_t ssel = (uint32_t)(((lane >> 3) & 1) * 16);

    auto prefetch = [&](int c, int buf) {
        uint32_t base = sb + (uint32_t)buf * 65536;
#pragma unroll
        for (int t = 0; t < 4; t++) {
            int idx = tid + t * 256;
            int row = idx >> 3, cc = idx & 7;
            uint32_t off = (uint32_t)row * 128 + (((uint32_t)cc * 16) ^ ((uint32_t)(row & 7) * 16));
            size_t xoff = (size_t)(r0 + row) * DM + c * 64 + cc * 8;
            size_t woff = (size_t)row * DM + c * 64 + cc * 8;
            CP_ASYNC16(base + off,         (const char*)(XH + xoff));
            CP_ASYNC16(base + 16384 + off, (const char*)(XL + xoff));
            CP_ASYNC16(base + 32768 + off, (const char*)(WH + woff));
            CP_ASYNC16(base + 49152 + off, (const char*)(WL + woff));
        }
    };

    prefetch(0, 0); CP_COMMIT();

    const int r = w * 16 + (lane & 15);
    const uint32_t rx = (uint32_t)((r & 7) * 16);

    for (int c = 0; c < 8; c++) {
        if (c + 1 < 8) { prefetch(c + 1, (c + 1) & 1); CP_COMMIT(); CP_WAIT1(); }
        else           { CP_WAIT0(); }
        __syncthreads();

        uint32_t base = sb + (uint32_t)(c & 1) * 65536;
#pragma unroll
        for (int kb = 0; kb < 4; kb++) {
            uint32_t aoff = (uint32_t)r * 128 +
                (((uint32_t)(kb * 32 + ((lane >> 4) * 16))) ^ rx);
            uint32_t ah[4], al[4];
            LDMX4(ah, base + aoff);
            LDMX4(al, base + 16384 + aoff);
#pragma unroll
            for (int nt = 0; nt < 16; nt++) {
                int n = nt * 8 + (lane & 7);
                uint32_t boff = (uint32_t)n * 128 +
                    (((uint32_t)(kb * 32) + ssel) ^ ((uint32_t)(n & 7) * 16));
                uint32_t bh0, bh1, bl0, bl1;
                LDMX2(bh0, bh1, base + 32768 + boff);
                LDMX2(bl0, bl1, base + 49152 + boff);
                MMA16816(acc[nt], ah, bh0, bh1);
                MMA16816(acc[nt], al, bh0, bh1);
                MMA16816(acc[nt], ah, bl0, bl1);
            }
        }
        __syncthreads();
    }

    const float scale = (z == 0) ? 0.125f : 1.0f;
    __nv_bfloat16* hd = (z == 0) ? g_qhi : (z == 1) ? g_khi : g_vhi;
    __nv_bfloat16* ld = (z == 0) ? g_qlo : (z == 1) ? g_klo : g_vlo;
    const int gr0 = r0 + w * 16 + (lane >> 2);
    const int cq = 2 * (lane & 3);
#pragma unroll
    for (int rr = 0; rr < 2; rr++) {
        int gr = gr0 + rr * 8;
        int bb = gr >> 11, n = gr & (NTOK - 1);
#pragma unroll
        for (int nt = 0; nt < 16; nt++) {
            int h = hp * 2 + (nt >> 3);
            int col = (nt & 7) * 8 + cq;
            size_t base = (((size_t)bb * NH + h) * NTOK + n) * DK + col;
            float v0 = acc[nt][2 * rr] * scale, v1 = acc[nt][2 * rr + 1] * scale;
            uint32_t l01;
            uint32_t h01 = pack_split(v0, v1, l01);
            *(uint32_t*)(hd + base) = h01;
            *(uint32_t*)(ld + base) = l01;
        }
    }
}

// ============================================================
// attention v3: triple-buffered cp.async, ONE barrier per tile,
// merged x4 ldmatrix for hi/lo fragment pairs
// smem: buf[3] x 32KB (KH|KL|VH|VL 8K each) + [98304 + buf*1024]: coords 768B, kpm
// ============================================================
#define ATTN_SMEM (98304 + 3072)
__global__ __launch_bounds__(256, 1) void attn_mma_kernel(
    const float* __restrict__ coords, const unsigned char* __restrict__ kpm)
{
    extern __shared__ __align__(16) char asm_sm[];
    char* sm = asm_sm;
    const uint32_t sb = smem_to_u32(sm);

    const int tid = threadIdx.x;
    const int lane = tid & 31;
    const int w = tid >> 5;
    const int b = blockIdx.z, h = blockIdx.y;
    const int q0 = blockIdx.x * 128;

    const float tpow   = 0.98f * (float)h / 7.0f;
    const float spread = 3.7f + (powf(20.0f, tpow) - 1.0f) * (16.3f / 19.0f);
    const float s2 = spread * spread;
    const float nine_s2 = 9.0f * s2;
    const float inv2s2 = 0.5f / s2;

    const size_t bh = ((size_t)b * NH + h) * NTOK;

    // stage Q into buf0 area (plain loads; once)
    {
        const __nv_bfloat16* qh_g = g_qhi + (bh + q0) * DK;
        const __nv_bfloat16* ql_g = g_qlo + (bh + q0) * DK;
#pragma unroll
        for (int t = 0; t < 4; t++) {
            int idx = tid + t * 256;
            int row = idx >> 3, c = idx & 7;
            uint32_t doff = (uint32_t)row * 128 + (((uint32_t)c * 16) ^ ((uint32_t)(row & 7) * 16));
            *(uint4*)(sm + doff)         = *(const uint4*)(qh_g + (size_t)row * DK + c * 8);
            *(uint4*)(sm + 16384 + doff) = *(const uint4*)(ql_g + (size_t)row * DK + c * 8);
        }
    }
    __syncthreads();

    uint32_t aqh[4][4], aql[4][4];
    {
        int r = w * 16 + (lane & 15);
        uint32_t rx = (uint32_t)((r & 7) * 16);
#pragma unroll
        for (int ks = 0; ks < 4; ks++) {
            uint32_t cb = (uint32_t)(ks * 32 + (lane >> 4) * 16);
            uint32_t off = (uint32_t)r * 128 + (cb ^ rx);
            LDMX4(aqh[ks], sb + off);
            LDMX4(aql[ks], sb + 16384 + off);
        }
    }
    __syncthreads();   // Q frags extracted before buf0 is overwritten

    const int g = lane >> 2;
    const int cq = 2 * (lane & 3);
    const int qr0 = q0 + w * 16 + g;
    float qx0, qy0, qz0, qx1, qy1, qz1;
    {
        const float* c0p = coords + ((size_t)b * NTOK + qr0) * 3;
        const float* c1p = c0p + 24;
        qx0 = c0p[0]; qy0 = c0p[1]; qz0 = c0p[2];
        qx1 = c1p[0]; qy1 = c1p[1]; qz1 = c1p[2];
    }

    float O[8][4];
#pragma unroll
    for (int i = 0; i < 8; i++) { O[i][0]=0.f; O[i][1]=0.f; O[i][2]=0.f; O[i][3]=0.f; }
    float mr0 = -INF_F, mr1 = -INF_F, lr0 = 0.f, lr1 = 0.f;

    const __nv_bfloat16* kh_g = g_khi + bh * DK;
    const __nv_bfloat16* kl_g = g_klo + bh * DK;
    const __nv_bfloat16* vh_g = g_vhi + bh * DK;
    const __nv_bfloat16* vl_g = g_vlo + bh * DK;

    auto prefetch = [&](int mtile, int buf) {
        uint32_t base = sb + (uint32_t)buf * 32768;
        int m0 = mtile * 64;
#pragma unroll
        for (int t = 0; t < 2; t++) {
            int idx = tid + t * 256;
            int row = idx >> 3, cc = idx & 7;
            uint32_t off = (uint32_t)row * 128 + (((uint32_t)cc * 16) ^ ((uint32_t)(row & 7) * 16));
            size_t goff = (size_t)(m0 + row) * DK + cc * 8;
            CP_ASYNC16(base + off,         (const char*)(kh_g + goff));
            CP_ASYNC16(base + 8192 + off,  (const char*)(kl_g + goff));
            CP_ASYNC16(base + 16384 + off, (const char*)(vh_g + goff));
            CP_ASYNC16(base + 24576 + off, (const char*)(vl_g + goff));
        }
        uint32_t cbase = sb + 98304 + (uint32_t)buf * 1024;
        if (tid < 48)
            CP_ASYNC16(cbase + tid * 16,
                       (const char*)coords + ((size_t)b * NTOK + m0) * 12 + tid * 16);
        else if (tid >= 64 && tid < 68)
            CP_ASYNC16(cbase + 768 + (tid - 64) * 16,
                       (const char*)(kpm + (size_t)b * NTOK + m0 + (tid - 64) * 16));
    };

    const uint32_t kxor = (uint32_t)(lane & 7) * 16;
    const uint32_t krow128 = (uint32_t)(lane & 7) * 128;
    const uint32_t ssel = (uint32_t)(((lane >> 3) & 1) * 16);
    const uint32_t vrow = (uint32_t)(lane & 15);
    const uint32_t hl = (lane >> 4) ? 8192u : 0u;   // lanes 16-31 -> lo region

    prefetch(0, 0); CP_COMMIT();

    int buf = 0;
    for (int mt = 0; mt < NTOK / 64; mt++) {
        if (mt + 1 < NTOK / 64) {
            int nbuf = (buf == 2) ? 0 : buf + 1;
            prefetch(mt + 1, nbuf); CP_COMMIT(); CP_WAIT1();
        } else {
            CP_WAIT0();
        }
        __syncthreads();   // the ONLY barrier per tile

        const uint32_t base = sb + (uint32_t)buf * 32768;
        const float* mc = (const float*)(sm + 98304 + (size_t)buf * 1024);
        const unsigned char* kpms = (const unsigned char*)(sm + 98304 + (size_t)buf * 1024 + 768);

        // ---- S ----
        float S[8][4];
#pragma unroll
        for (int i = 0; i < 8; i++) { S[i][0]=0.f; S[i][1]=0.f; S[i][2]=0.f; S[i][3]=0.f; }
#pragma unroll
        for (int ks = 0; ks < 4; ks++) {
            uint32_t cb = (((uint32_t)(ks * 32)) + ssel) ^ kxor;
#pragma unroll
            for (int nt = 0; nt < 8; nt++) {
                uint32_t off = (uint32_t)nt * 1024 + krow128 + cb + hl;
                uint32_t r4[4];
                LDMX4(r4, base + off);           // khi (2 frags) + klo (2 frags)
                MMA16816(S[nt], aqh[ks], r4[0], r4[1]);
                MMA16816(S[nt], aql[ks], r4[0], r4[1]);
                MMA16816(S[nt], aqh[ks], r4[2], r4[3]);
            }
        }

        // ---- epilogue pass A ----
        float rm0 = -INF_F, rm1 = -INF_F;
#pragma unroll
        for (int nt = 0; nt < 8; nt++) {
            int m0c = nt * 8 + cq;
            float k0x = mc[m0c*3+0], k0y = mc[m0c*3+1], k0z = mc[m0c*3+2];
            float k1x = mc[m0c*3+3], k1y = mc[m0c*3+4], k1z = mc[m0c*3+5];
            bool p0 = kpms[m0c] != 0, p1 = kpms[m0c+1] != 0;
            {
                float dx=qx0-k0x, dy=qy0-k0y, dz=qz0-k0z;
                float d2 = dx*dx+dy*dy+dz*dz;
                float s = S[nt][0];
                float v = s * __expf(copysignf(fmaxf(d2, s2)*inv2s2, -s));
                v = (d2 > nine_s2 || p0) ? -INF_F : v;
                S[nt][0]=v; rm0=fmaxf(rm0,v);
            }
            {
                float dx=qx0-k1x, dy=qy0-k1y, dz=qz0-k1z;
                float d2 = dx*dx+dy*dy+dz*dz;
                float s = S[nt][1];
                float v = s * __expf(copysignf(fmaxf(d2, s2)*inv2s2, -s));
                v = (d2 > nine_s2 || p1) ? -INF_F : v;
                S[nt][1]=v; rm0=fmaxf(rm0,v);
            }
            {
                float dx=qx1-k0x, dy=qy1-k0y, dz=qz1-k0z;
                float d2 = dx*dx+dy*dy+dz*dz;
                float s = S[nt][2];
                float v = s * __expf(copysignf(fmaxf(d2, s2)*inv2s2, -s));
                v = (d2 > nine_s2 || p0) ? -INF_F : v;
                S[nt][2]=v; rm1=fmaxf(rm1,v);
            }
            {
                float dx=qx1-k1x, dy=qy1-k1y, dz=qz1-k1z;
                float d2 = dx*dx+dy*dy+dz*dz;
                float s = S[nt][3];
                float v = s * __expf(copysignf(fmaxf(d2, s2)*inv2s2, -s));
                v = (d2 > nine_s2 || p1) ? -INF_F : v;
                S[nt][3]=v; rm1=fmaxf(rm1,v);
            }
        }
        rm0 = fmaxf(rm0, __shfl_xor_sync(0xffffffffu, rm0, 1));
        rm0 = fmaxf(rm0, __shfl_xor_sync(0xffffffffu, rm0, 2));
        rm1 = fmaxf(rm1, __shfl_xor_sync(0xffffffffu, rm1, 1));
        rm1 = fmaxf(rm1, __shfl_xor_sync(0xffffffffu, rm1, 2));

        float nm0 = fmaxf(mr0, rm0), nm1 = fmaxf(mr1, rm1);
        bool dead0 = (nm0 == -INF_F), dead1 = (nm1 == -INF_F);
        float cf0 = dead0 ? 1.f : __expf(mr0 - nm0);
        float cf1 = dead1 ? 1.f : __expf(mr1 - nm1);
#pragma unroll
        for (int nt = 0; nt < 8; nt++) {
            O[nt][0] *= cf0; O[nt][1] *= cf0;
            O[nt][2] *= cf1; O[nt][3] *= cf1;
        }
        float rs0 = 0.f, rs1 = 0.f;
#pragma unroll
        for (int nt = 0; nt < 8; nt++) {
            float p0 = dead0 ? 0.f : __expf(S[nt][0] - nm0);
            float p1 = dead0 ? 0.f : __expf(S[nt][1] - nm0);
            float p2 = dead1 ? 0.f : __expf(S[nt][2] - nm1);
            float p3 = dead1 ? 0.f : __expf(S[nt][3] - nm1);
            rs0 += p0 + p1; rs1 += p2 + p3;
            S[nt][0] = p0; S[nt][1] = p1; S[nt][2] = p2; S[nt][3] = p3;
        }
        rs0 += __shfl_xor_sync(0xffffffffu, rs0, 1);
        rs0 += __shfl_xor_sync(0xffffffffu, rs0, 2);
        rs1 += __shfl_xor_sync(0xffffffffu, rs1, 1);
        rs1 += __shfl_xor_sync(0xffffffffu, rs1, 2);
        lr0 = lr0 * cf0 + rs0; lr1 = lr1 * cf1 + rs1;
        mr0 = nm0; mr1 = nm1;

        uint32_t ph[4][4], pl[4][4];
#pragma unroll
        for (int ks = 0; ks < 4; ks++) {
            int t0 = 2 * ks, t1 = t0 + 1;
            ph[ks][0] = pack_split(S[t0][0], S[t0][1], pl[ks][0]);
            ph[ks][1] = pack_split(S[t0][2], S[t0][3], pl[ks][1]);
            ph[ks][2] = pack_split(S[t1][0], S[t1][1], pl[ks][2]);
            ph[ks][3] = pack_split(S[t1][2], S[t1][3], pl[ks][3]);
        }

        // ---- O += P V ----
#pragma unroll
        for (int ks = 0; ks < 4; ks++) {
            uint32_t roff = (uint32_t)(ks * 16 + vrow) * 128;
#pragma unroll
            for (int nt = 0; nt < 8; nt++) {
                uint32_t off = roff + (((uint32_t)nt * 16) ^ kxor) + hl;
                uint32_t r4[4];
                LDMX4T(r4, base + 16384 + off);  // vhi (2 frags) + vlo (2 frags)
                MMA16816(O[nt], ph[ks], r4[0], r4[1]);
                MMA16816(O[nt], pl[ks], r4[0], r4[1]);
                MMA16816(O[nt], ph[ks], r4[2], r4[3]);
            }
        }
        buf = (buf == 2) ? 0 : buf + 1;
        // no trailing barrier: 3rd buffer makes warp drift safe
    }

    float inv0 = 1.f / lr0, inv1 = 1.f / lr1;
    float* orow0 = g_o + ((size_t)b * NTOK + qr0) * DM + h * DK;
    float* orow1 = orow0 + 8 * DM;
#pragma unroll
    for (int nt = 0; nt < 8; nt++) {
        *(float2*)(orow0 + nt * 8 + cq) = make_float2(O[nt][0] * inv0, O[nt][1] * inv0);
        *(float2*)(orow1 + nt * 8 + cq) = make_float2(O[nt][2] * inv1, O[nt][3] * inv1);
    }
}

// ============================================================
// outproj (R6, proven)
// ============================================================
__global__ __launch_bounds__(256) void outproj_mma_kernel(
    const float* __restrict__ ow, const float* __restrict__ ob, float* __restrict__ out)
{
    __shared__ __align__(16) char sm[49152];
    const uint32_t sb = smem_to_u32(sm);
    char* AH = sm;          char* AL = sm + 16384;
    char* BH = sm + 32768;  char* BL = sm + 40960;

    const int tid = threadIdx.x;
    const int lane = tid & 31, w = tid >> 5;
    const int c0 = blockIdx.x * 64, r0 = blockIdx.y * 128;

    float acc[8][4];
#pragma unroll
    for (int i = 0; i < 8; i++) { acc[i][0]=0.f; acc[i][1]=0.f; acc[i][2]=0.f; acc[i][3]=0.f; }

    const uint32_t ssel = (uint32_t)(((lane >> 3) & 1) * 16);

    for (int k0 = 0; k0 < DM; k0 += 32) {
#pragma unroll
        for (int t = 0; t < 2; t++) {
            int p = tid + t * 256;
            int row = p >> 2, ch = p & 3;
            uint32_t off = (uint32_t)row * 128 + (((uint32_t)ch * 16) ^ ((uint32_t)(row & 7) * 16));
            stage8(g_o + (size_t)(r0 + row) * DM + k0 + ch * 8, AH + off, AL + off);
        }
        {
            int p = tid;
            int row = p >> 2, ch = p & 3;
            uint32_t off = (uint32_t)row * 128 + (((uint32_t)ch * 16) ^ ((uint32_t)(row & 7) * 16));
            stage8(ow + (size_t)(c0 + row) * DM + k0 + ch * 8, BH + off, BL + off);
        }
        __syncthreads();

#pragma unroll
        for (int kb = 0; kb < 2; kb++) {
            int r = w * 16 + (lane & 15);
            uint32_t aoff = (uint32_t)r * 128 +
                (((uint32_t)(kb * 32 + ((lane >> 4) * 16))) ^ ((uint32_t)(r & 7) * 16));
            uint32_t ah[4], al[4];
            LDMX4(ah, sb + (uint32_t)(AH - sm) + aoff);
            LDMX4(al, sb + (uint32_t)(AL - sm) + aoff);
#pragma unroll
            for (int nt = 0; nt < 8; nt++) {
                int n = nt * 8 + (lane & 7);
                uint32_t boff = (uint32_t)n * 128 +
                    (((uint32_t)(kb * 32) + ssel) ^ ((uint32_t)(n & 7) * 16));
                uint32_t bh0, bh1, bl0, bl1;
                LDMX2(bh0, bh1, sb + (uint32_t)(BH - sm) + boff);
                LDMX2(bl0, bl1, sb + (uint32_t)(BL - sm) + boff);
                MMA16816(acc[nt], ah, bh0, bh1);
                MMA16816(acc[nt], al, bh0, bh1);
                MMA16816(acc[nt], ah, bl0, bl1);
            }
        }
        __syncthreads();
    }

    const int gr0 = r0 + w * 16 + (lane >> 2);
    const int cq = 2 * (lane & 3);
#pragma unroll
    for (int rr = 0; rr < 2; rr++) {
        int gr = gr0 + rr * 8;
        float* orow = out + (size_t)gr * DM + c0;
#pragma unroll
        for (int nt = 0; nt < 8; nt++) {
            int col = nt * 8 + cq;
            float2 bias = *(const float2*)(ob + c0 + col);
            *(float2*)(orow + col) = make_float2(acc[nt][2 * rr] + bias.x,
                                                 acc[nt][2 * rr + 1] + bias.y);
        }
    }
}

// ---------------------------------------------------------------------------
extern "C" void kernel_launch(void* const* d_in, const int* in_sizes, int n_in,
                              void* d_out, int out_size)
{
    const float* q      = (const float*)d_in[0];
    const float* k      = (const float*)d_in[1];
    const float* v      = (const float*)d_in[2];
    const float* coords = (const float*)d_in[3];
    const unsigned char* kpm = (const unsigned char*)d_in[4];
    const float* qp     = (const float*)d_in[5];
    const float* kpj    = (const float*)d_in[6];
    const float* vp     = (const float*)d_in[7];
    const float* ow     = (const float*)d_in[8];
    const float* ob     = (const float*)d_in[9];
    float* out = (float*)d_out;

    static int attr_set = 0;
    if (!attr_set) {
        cudaFuncSetAttribute(proj_mma_kernel, cudaFuncAttributeMaxDynamicSharedMemorySize, PROJ_SMEM);
        cudaFuncSetAttribute(attn_mma_kernel, cudaFuncAttributeMaxDynamicSharedMemorySize, ATTN_SMEM);
        attr_set = 1;
    }

    presplit_x_kernel<<<dim3(1024, 3), 256>>>(q, k, v);
    presplit_w_kernel<<<dim3(128, 3), 256>>>(qp, kpj, vp);
    proj_mma_kernel<<<dim3(4, 32, 3), 256, PROJ_SMEM>>>();
    attn_mma_kernel<<<dim3(NTOK / 128, NH, B_SZ), 256, ATTN_SMEM>>>(coords, kpm);
    outproj_mma_kernel<<<dim3(8, 32), 256>>>(ow, ob, out);
}

// round 13
// speedup vs baseline: 2.9868x; 1.0254x over previous
#include <cuda_runtime.h>
#include <cuda_bf16.h>
#include <math.h>
#include <cstdint>

#define B_SZ 2
#define NTOK 2048
#define NH 8
#define DK 64
#define DM 512
#define INF_F __int_as_float(0x7f800000)

// device scratch
__device__ float g_o[B_SZ * NTOK * DM];
__device__ __align__(16) __nv_bfloat16 g_qhi[B_SZ * NH * NTOK * DK];
__device__ __align__(16) __nv_bfloat16 g_qlo[B_SZ * NH * NTOK * DK];
__device__ __align__(16) __nv_bfloat16 g_khi[B_SZ * NH * NTOK * DK];
__device__ __align__(16) __nv_bfloat16 g_klo[B_SZ * NH * NTOK * DK];
__device__ __align__(16) __nv_bfloat16 g_vhi[B_SZ * NH * NTOK * DK];
__device__ __align__(16) __nv_bfloat16 g_vlo[B_SZ * NH * NTOK * DK];
// pre-split inputs: [z][b][n][d]
__device__ __align__(16) __nv_bfloat16 g_xhi[3 * B_SZ * NTOK * DM];
__device__ __align__(16) __nv_bfloat16 g_xlo[3 * B_SZ * NTOK * DM];
// pre-split transposed weights: [z][h][n][k]
__device__ __align__(16) __nv_bfloat16 g_whi[3 * NH * DK * DM];
__device__ __align__(16) __nv_bfloat16 g_wlo[3 * NH * DK * DM];

// ---------------- helpers ----------------
__device__ __forceinline__ uint32_t smem_to_u32(const void* p) {
    uint32_t a;
    asm("{ .reg .u64 t; cvta.to.shared.u64 t, %1; cvt.u32.u64 %0, t; }" : "=r"(a) : "l"(p));
    return a;
}

#define LDMX2(r0, r1, addr) \
    asm volatile("ldmatrix.sync.aligned.m8n8.x2.shared.b16 {%0,%1}, [%2];" \
        : "=r"(r0), "=r"(r1) : "r"(addr))
#define LDMX4(r, addr) \
    asm volatile("ldmatrix.sync.aligned.m8n8.x4.shared.b16 {%0,%1,%2,%3}, [%4];" \
        : "=r"((r)[0]), "=r"((r)[1]), "=r"((r)[2]), "=r"((r)[3]) : "r"(addr))
#define LDMX4T(r, addr) \
    asm volatile("ldmatrix.sync.aligned.m8n8.x4.trans.shared.b16 {%0,%1,%2,%3}, [%4];" \
        : "=r"((r)[0]), "=r"((r)[1]), "=r"((r)[2]), "=r"((r)[3]) : "r"(addr))
#define MMA16816(d, a, b0, b1) \
    asm volatile("mma.sync.aligned.m16n8k16.row.col.f32.bf16.bf16.f32 " \
        "{%0,%1,%2,%3}, {%4,%5,%6,%7}, {%8,%9}, {%0,%1,%2,%3};" \
        : "+f"((d)[0]), "+f"((d)[1]), "+f"((d)[2]), "+f"((d)[3]) \
        : "r"((a)[0]), "r"((a)[1]), "r"((a)[2]), "r"((a)[3]), "r"(b0), "r"(b1))

#define CP_ASYNC16(dst, src) \
    asm volatile("cp.async.cg.shared.global [%0], [%1], 16;" :: "r"(dst), "l"(src) : "memory")
#define CP_COMMIT()  asm volatile("cp.async.commit_group;" ::: "memory")
#define CP_WAIT1()   asm volatile("cp.async.wait_group 1;" ::: "memory")
#define CP_WAIT0()   asm volatile("cp.async.wait_group 0;" ::: "memory")

__device__ __forceinline__ uint32_t pack_split(float a, float b, uint32_t& lo) {
    __nv_bfloat162 hv = __float22bfloat162_rn(make_float2(a, b));
    float ra = a - __low2float(hv);
    float rb = b - __high2float(hv);
    __nv_bfloat162 lv = __float22bfloat162_rn(make_float2(ra, rb));
    lo = *reinterpret_cast<uint32_t*>(&lv);
    return *reinterpret_cast<uint32_t*>(&hv);
}

__device__ __forceinline__ void stage8(const float* __restrict__ src,
                                       char* hi_dst, char* lo_dst)
{
    float4 a = ((const float4*)src)[0];
    float4 b = ((const float4*)src)[1];
    uint32_t l0, l1, l2, l3;
    uint32_t h0 = pack_split(a.x, a.y, l0);
    uint32_t h1 = pack_split(a.z, a.w, l1);
    uint32_t h2 = pack_split(b.x, b.y, l2);
    uint32_t h3 = pack_split(b.z, b.w, l3);
    *(uint4*)hi_dst = make_uint4(h0, h1, h2, h3);
    *(uint4*)lo_dst = make_uint4(l0, l1, l2, l3);
}

// ============================================================
// pre-split kernels
// ============================================================
__global__ __launch_bounds__(256) void presplit_x_kernel(
    const float* __restrict__ q, const float* __restrict__ k, const float* __restrict__ v)
{
    const int z = blockIdx.y;
    const float* X = (z == 0) ? q : (z == 1) ? k : v;
    size_t off = ((size_t)blockIdx.x * 256 + threadIdx.x) * 8;
    size_t base = (size_t)z * (B_SZ * NTOK * DM) + off;
    stage8(X + off, (char*)(g_xhi + base), (char*)(g_xlo + base));
}

__global__ __launch_bounds__(256) void presplit_w_kernel(
    const float* __restrict__ qp, const float* __restrict__ kpj, const float* __restrict__ vp)
{
    const int z = blockIdx.y;
    const float* W = (z == 0) ? qp : (z == 1) ? kpj : vp;
    int t = blockIdx.x * 256 + threadIdx.x;
    int kc = t & 63, n = (t >> 6) & 63, h = t >> 12;
    int k0 = kc * 8;
    float f[8];
#pragma unroll
    for (int e = 0; e < 8; e++)
        f[e] = W[(size_t)h * DM * DK + (size_t)(k0 + e) * DK + n];
    uint32_t hp[4], lp[4];
#pragma unroll
    for (int e = 0; e < 4; e++)
        hp[e] = pack_split(f[2*e], f[2*e+1], lp[e]);
    size_t base = (((size_t)z * NH + h) * DK + n) * DM + k0;
    *(uint4*)(g_whi + base) = make_uint4(hp[0], hp[1], hp[2], hp[3]);
    *(uint4*)(g_wlo + base) = make_uint4(lp[0], lp[1], lp[2], lp[3]);
}

// ============================================================
// proj v2 (R8, proven): cp.async double-buffered
// ============================================================
#define PROJ_SMEM 131072
__global__ __launch_bounds__(256) void proj_mma_kernel()
{
    extern __shared__ __align__(16) char dsm[];
    const uint32_t sb = smem_to_u32(dsm);

    const int tid = threadIdx.x;
    const int lane = tid & 31, w = tid >> 5;
    const int hp = blockIdx.x;
    const int r0 = blockIdx.y * 128;
    const int z  = blockIdx.z;

    const __nv_bfloat16* XH = g_xhi + (size_t)z * (B_SZ * NTOK * DM);
    const __nv_bfloat16* XL = g_xlo + (size_t)z * (B_SZ * NTOK * DM);
    const __nv_bfloat16* WH = g_whi + ((size_t)z * NH + hp * 2) * DK * DM;
    const __nv_bfloat16* WL = g_wlo + ((size_t)z * NH + hp * 2) * DK * DM;

    float acc[16][4];
#pragma unroll
    for (int i = 0; i < 16; i++) { acc[i][0]=0.f; acc[i][1]=0.f; acc[i][2]=0.f; acc[i][3]=0.f; }

    const uint32_t ssel = (uint32_t)(((lane >> 3) & 1) * 16);

    auto prefetch = [&](int c, int buf) {
        uint32_t base = sb + (uint32_t)buf * 65536;
#pragma unroll
        for (int t = 0; t < 4; t++) {
            int idx = tid + t * 256;
            int row = idx >> 3, cc = idx & 7;
            uint32_t off = (uint32_t)row * 128 + (((uint32_t)cc * 16) ^ ((uint32_t)(row & 7) * 16));
            size_t xoff = (size_t)(r0 + row) * DM + c * 64 + cc * 8;
            size_t woff = (size_t)row * DM + c * 64 + cc * 8;
            CP_ASYNC16(base + off,         (const char*)(XH + xoff));
            CP_ASYNC16(base + 16384 + off, (const char*)(XL + xoff));
            CP_ASYNC16(base + 32768 + off, (const char*)(WH + woff));
            CP_ASYNC16(base + 49152 + off, (const char*)(WL + woff));
        }
    };

    prefetch(0, 0); CP_COMMIT();

    const int r = w * 16 + (lane & 15);
    const uint32_t rx = (uint32_t)((r & 7) * 16);

    for (int c = 0; c < 8; c++) {
        if (c + 1 < 8) { prefetch(c + 1, (c + 1) & 1); CP_COMMIT(); CP_WAIT1(); }
        else           { CP_WAIT0(); }
        __syncthreads();

        uint32_t base = sb + (uint32_t)(c & 1) * 65536;
#pragma unroll
        for (int kb = 0; kb < 4; kb++) {
            uint32_t aoff = (uint32_t)r * 128 +
                (((uint32_t)(kb * 32 + ((lane >> 4) * 16))) ^ rx);
            uint32_t ah[4], al[4];
            LDMX4(ah, base + aoff);
            LDMX4(al, base + 16384 + aoff);
#pragma unroll
            for (int nt = 0; nt < 16; nt++) {
                int n = nt * 8 + (lane & 7);
                uint32_t boff = (uint32_t)n * 128 +
                    (((uint32_t)(kb * 32) + ssel) ^ ((uint32_t)(n & 7) * 16));
                uint32_t bh0, bh1, bl0, bl1;
                LDMX2(bh0, bh1, base + 32768 + boff);
                LDMX2(bl0, bl1, base + 49152 + boff);
                MMA16816(acc[nt], ah, bh0, bh1);
                MMA16816(acc[nt], al, bh0, bh1);
                MMA16816(acc[nt], ah, bl0, bl1);
            }
        }
        __syncthreads();
    }

    const float scale = (z == 0) ? 0.125f : 1.0f;
    __nv_bfloat16* hd = (z == 0) ? g_qhi : (z == 1) ? g_khi : g_vhi;
    __nv_bfloat16* ld = (z == 0) ? g_qlo : (z == 1) ? g_klo : g_vlo;
    const int gr0 = r0 + w * 16 + (lane >> 2);
    const int cq = 2 * (lane & 3);
#pragma unroll
    for (int rr = 0; rr < 2; rr++) {
        int gr = gr0 + rr * 8;
        int bb = gr >> 11, n = gr & (NTOK - 1);
#pragma unroll
        for (int nt = 0; nt < 16; nt++) {
            int h = hp * 2 + (nt >> 3);
            int col = (nt & 7) * 8 + cq;
            size_t base = (((size_t)bb * NH + h) * NTOK + n) * DK + col;
            float v0 = acc[nt][2 * rr] * scale, v1 = acc[nt][2 * rr + 1] * scale;
            uint32_t l01;
            uint32_t h01 = pack_split(v0, v1, l01);
            *(uint32_t*)(hd + base) = h01;
            *(uint32_t*)(ld + base) = l01;
        }
    }
}

// ============================================================
// attention v4: q-tile 64, 128-thread CTAs, 2 CTAs/SM.
// Per-warp program identical to v3. Triple-buffered cp.async, one barrier/tile.
// smem: buf[3] x 32KB (KH|KL|VH|VL 8K each) + [98304 + buf*1024]: coords 768B, kpm
// ============================================================
#define ATTN_SMEM (98304 + 3072)
__global__ __launch_bounds__(128, 2) void attn_mma_kernel(
    const float* __restrict__ coords, const unsigned char* __restrict__ kpm)
{
    extern __shared__ __align__(16) char asm_sm[];
    char* sm = asm_sm;
    const uint32_t sb = smem_to_u32(sm);

    const int tid = threadIdx.x;
    const int lane = tid & 31;
    const int w = tid >> 5;          // 0..3
    const int b = blockIdx.z, h = blockIdx.y;
    const int q0 = blockIdx.x * 64;

    const float tpow   = 0.98f * (float)h / 7.0f;
    const float spread = 3.7f + (powf(20.0f, tpow) - 1.0f) * (16.3f / 19.0f);
    const float s2 = spread * spread;
    const float nine_s2 = 9.0f * s2;
    const float inv2s2 = 0.5f / s2;

    const size_t bh = ((size_t)b * NH + h) * NTOK;

    // stage Q (64 rows) into buf0 area (plain loads; once)
    {
        const __nv_bfloat16* qh_g = g_qhi + (bh + q0) * DK;
        const __nv_bfloat16* ql_g = g_qlo + (bh + q0) * DK;
#pragma unroll
        for (int t = 0; t < 4; t++) {
            int idx = tid + t * 128;   // 0..511 covers 64 rows x 8 cols
            int row = idx >> 3, c = idx & 7;
            uint32_t doff = (uint32_t)row * 128 + (((uint32_t)c * 16) ^ ((uint32_t)(row & 7) * 16));
            *(uint4*)(sm + doff)         = *(const uint4*)(qh_g + (size_t)row * DK + c * 8);
            *(uint4*)(sm + 8192 + doff)  = *(const uint4*)(ql_g + (size_t)row * DK + c * 8);
        }
    }
    __syncthreads();

    uint32_t aqh[4][4], aql[4][4];
    {
        int r = w * 16 + (lane & 15);
        uint32_t rx = (uint32_t)((r & 7) * 16);
#pragma unroll
        for (int ks = 0; ks < 4; ks++) {
            uint32_t cb = (uint32_t)(ks * 32 + (lane >> 4) * 16);
            uint32_t off = (uint32_t)r * 128 + (cb ^ rx);
            LDMX4(aqh[ks], sb + off);
            LDMX4(aql[ks], sb + 8192 + off);
        }
    }
    __syncthreads();   // Q frags extracted before buf0 is overwritten

    const int g = lane >> 2;
    const int cq = 2 * (lane & 3);
    const int qr0 = q0 + w * 16 + g;
    float qx0, qy0, qz0, qx1, qy1, qz1;
    {
        const float* c0p = coords + ((size_t)b * NTOK + qr0) * 3;
        const float* c1p = c0p + 24;
        qx0 = c0p[0]; qy0 = c0p[1]; qz0 = c0p[2];
        qx1 = c1p[0]; qy1 = c1p[1]; qz1 = c1p[2];
    }

    float O[8][4];
#pragma unroll
    for (int i = 0; i < 8; i++) { O[i][0]=0.f; O[i][1]=0.f; O[i][2]=0.f; O[i][3]=0.f; }
    float mr0 = -INF_F, mr1 = -INF_F, lr0 = 0.f, lr1 = 0.f;

    const __nv_bfloat16* kh_g = g_khi + bh * DK;
    const __nv_bfloat16* kl_g = g_klo + bh * DK;
    const __nv_bfloat16* vh_g = g_vhi + bh * DK;
    const __nv_bfloat16* vl_g = g_vlo + bh * DK;

    auto prefetch = [&](int mtile, int buf) {
        uint32_t base = sb + (uint32_t)buf * 32768;
        int m0 = mtile * 64;
#pragma unroll
        for (int t = 0; t < 4; t++) {
            int idx = tid + t * 128;   // 0..511
            int row = idx >> 3, cc = idx & 7;
            uint32_t off = (uint32_t)row * 128 + (((uint32_t)cc * 16) ^ ((uint32_t)(row & 7) * 16));
            size_t goff = (size_t)(m0 + row) * DK + cc * 8;
            CP_ASYNC16(base + off,         (const char*)(kh_g + goff));
            CP_ASYNC16(base + 8192 + off,  (const char*)(kl_g + goff));
            CP_ASYNC16(base + 16384 + off, (const char*)(vh_g + goff));
            CP_ASYNC16(base + 24576 + off, (const char*)(vl_g + goff));
        }
        uint32_t cbase = sb + 98304 + (uint32_t)buf * 1024;
        if (tid < 48)
            CP_ASYNC16(cbase + tid * 16,
                       (const char*)coords + ((size_t)b * NTOK + m0) * 12 + tid * 16);
        else if (tid >= 64 && tid < 68)
            CP_ASYNC16(cbase + 768 + (tid - 64) * 16,
                       (const char*)(kpm + (size_t)b * NTOK + m0 + (tid - 64) * 16));
    };

    const uint32_t kxor = (uint32_t)(lane & 7) * 16;
    const uint32_t krow128 = (uint32_t)(lane & 7) * 128;
    const uint32_t ssel = (uint32_t)(((lane >> 3) & 1) * 16);
    const uint32_t vrow = (uint32_t)(lane & 15);
    const uint32_t hl = (lane >> 4) ? 8192u : 0u;   // lanes 16-31 -> lo region

    prefetch(0, 0); CP_COMMIT();

    int buf = 0;
    for (int mt = 0; mt < NTOK / 64; mt++) {
        if (mt + 1 < NTOK / 64) {
            int nbuf = (buf == 2) ? 0 : buf + 1;
            prefetch(mt + 1, nbuf); CP_COMMIT(); CP_WAIT1();
        } else {
            CP_WAIT0();
        }
        __syncthreads();   // the ONLY barrier per tile (4 warps)

        const uint32_t base = sb + (uint32_t)buf * 32768;
        const float* mc = (const float*)(sm + 98304 + (size_t)buf * 1024);
        const unsigned char* kpms = (const unsigned char*)(sm + 98304 + (size_t)buf * 1024 + 768);

        // ---- S ----
        float S[8][4];
#pragma unroll
        for (int i = 0; i < 8; i++) { S[i][0]=0.f; S[i][1]=0.f; S[i][2]=0.f; S[i][3]=0.f; }
#pragma unroll
        for (int ks = 0; ks < 4; ks++) {
            uint32_t cb = (((uint32_t)(ks * 32)) + ssel) ^ kxor;
#pragma unroll
            for (int nt = 0; nt < 8; nt++) {
                uint32_t off = (uint32_t)nt * 1024 + krow128 + cb + hl;
                uint32_t r4[4];
                LDMX4(r4, base + off);           // khi (2 frags) + klo (2 frags)
                MMA16816(S[nt], aqh[ks], r4[0], r4[1]);
                MMA16816(S[nt], aql[ks], r4[0], r4[1]);
                MMA16816(S[nt], aqh[ks], r4[2], r4[3]);
            }
        }

        // ---- epilogue pass A ----
        float rm0 = -INF_F, rm1 = -INF_F;
#pragma unroll
        for (int nt = 0; nt < 8; nt++) {
            int m0c = nt * 8 + cq;
            float k0x = mc[m0c*3+0], k0y = mc[m0c*3+1], k0z = mc[m0c*3+2];
            float k1x = mc[m0c*3+3], k1y = mc[m0c*3+4], k1z = mc[m0c*3+5];
            bool p0 = kpms[m0c] != 0, p1 = kpms[m0c+1] != 0;
            {
                float dx=qx0-k0x, dy=qy0-k0y, dz=qz0-k0z;
                float d2 = dx*dx+dy*dy+dz*dz;
                float s = S[nt][0];
                float v = s * __expf(copysignf(fmaxf(d2, s2)*inv2s2, -s));
                v = (d2 > nine_s2 || p0) ? -INF_F : v;
                S[nt][0]=v; rm0=fmaxf(rm0,v);
            }
            {
                float dx=qx0-k1x, dy=qy0-k1y, dz=qz0-k1z;
                float d2 = dx*dx+dy*dy+dz*dz;
                float s = S[nt][1];
                float v = s * __expf(copysignf(fmaxf(d2, s2)*inv2s2, -s));
                v = (d2 > nine_s2 || p1) ? -INF_F : v;
                S[nt][1]=v; rm0=fmaxf(rm0,v);
            }
            {
                float dx=qx1-k0x, dy=qy1-k0y, dz=qz1-k0z;
                float d2 = dx*dx+dy*dy+dz*dz;
                float s = S[nt][2];
                float v = s * __expf(copysignf(fmaxf(d2, s2)*inv2s2, -s));
                v = (d2 > nine_s2 || p0) ? -INF_F : v;
                S[nt][2]=v; rm1=fmaxf(rm1,v);
            }
            {
                float dx=qx1-k1x, dy=qy1-k1y, dz=qz1-k1z;
                float d2 = dx*dx+dy*dy+dz*dz;
                float s = S[nt][3];
                float v = s * __expf(copysignf(fmaxf(d2, s2)*inv2s2, -s));
                v = (d2 > nine_s2 || p1) ? -INF_F : v;
                S[nt][3]=v; rm1=fmaxf(rm1,v);
            }
        }
        rm0 = fmaxf(rm0, __shfl_xor_sync(0xffffffffu, rm0, 1));
        rm0 = fmaxf(rm0, __shfl_xor_sync(0xffffffffu, rm0, 2));
        rm1 = fmaxf(rm1, __shfl_xor_sync(0xffffffffu, rm1, 1));
        rm1 = fmaxf(rm1, __shfl_xor_sync(0xffffffffu, rm1, 2));

        float nm0 = fmaxf(mr0, rm0), nm1 = fmaxf(mr1, rm1);
        bool dead0 = (nm0 == -INF_F), dead1 = (nm1 == -INF_F);
        float cf0 = dead0 ? 1.f : __expf(mr0 - nm0);
        float cf1 = dead1 ? 1.f : __expf(mr1 - nm1);
#pragma unroll
        for (int nt = 0; nt < 8; nt++) {
            O[nt][0] *= cf0; O[nt][1] *= cf0;
            O[nt][2] *= cf1; O[nt][3] *= cf1;
        }
        float rs0 = 0.f, rs1 = 0.f;
#pragma unroll
        for (int nt = 0; nt < 8; nt++) {
            float p0 = dead0 ? 0.f : __expf(S[nt][0] - nm0);
            float p1 = dead0 ? 0.f : __expf(S[nt][1] - nm0);
            float p2 = dead1 ? 0.f : __expf(S[nt][2] - nm1);
            float p3 = dead1 ? 0.f : __expf(S[nt][3] - nm1);
            rs0 += p0 + p1; rs1 += p2 + p3;
            S[nt][0] = p0; S[nt][1] = p1; S[nt][2] = p2; S[nt][3] = p3;
        }
        rs0 += __shfl_xor_sync(0xffffffffu, rs0, 1);
        rs0 += __shfl_xor_sync(0xffffffffu, rs0, 2);
        rs1 += __shfl_xor_sync(0xffffffffu, rs1, 1);
        rs1 += __shfl_xor_sync(0xffffffffu, rs1, 2);
        lr0 = lr0 * cf0 + rs0; lr1 = lr1 * cf1 + rs1;
        mr0 = nm0; mr1 = nm1;

        uint32_t ph[4][4], pl[4][4];
#pragma unroll
        for (int ks = 0; ks < 4; ks++) {
            int t0 = 2 * ks, t1 = t0 + 1;
            ph[ks][0] = pack_split(S[t0][0], S[t0][1], pl[ks][0]);
            ph[ks][1] = pack_split(S[t0][2], S[t0][3], pl[ks][1]);
            ph[ks][2] = pack_split(S[t1][0], S[t1][1], pl[ks][2]);
            ph[ks][3] = pack_split(S[t1][2], S[t1][3], pl[ks][3]);
        }

        // ---- O += P V ----
#pragma unroll
        for (int ks = 0; ks < 4; ks++) {
            uint32_t roff = (uint32_t)(ks * 16 + vrow) * 128;
#pragma unroll
            for (int nt = 0; nt < 8; nt++) {
                uint32_t off = roff + (((uint32_t)nt * 16) ^ kxor) + hl;
                uint32_t r4[4];
                LDMX4T(r4, base + 16384 + off);  // vhi (2 frags) + vlo (2 frags)
                MMA16816(O[nt], ph[ks], r4[0], r4[1]);
                MMA16816(O[nt], pl[ks], r4[0], r4[1]);
                MMA16816(O[nt], ph[ks], r4[2], r4[3]);
            }
        }
        buf = (buf == 2) ? 0 : buf + 1;
        // no trailing barrier: 3rd buffer makes warp drift safe
    }

    float inv0 = 1.f / lr0, inv1 = 1.f / lr1;
    float* orow0 = g_o + ((size_t)b * NTOK + qr0) * DM + h * DK;
    float* orow1 = orow0 + 8 * DM;
#pragma unroll
    for (int nt = 0; nt < 8; nt++) {
        *(float2*)(orow0 + nt * 8 + cq) = make_float2(O[nt][0] * inv0, O[nt][1] * inv0);
        *(float2*)(orow1 + nt * 8 + cq) = make_float2(O[nt][2] * inv1, O[nt][3] * inv1);
    }
}

// ============================================================
// outproj (R6, proven)
// ============================================================
__global__ __launch_bounds__(256) void outproj_mma_kernel(
    const float* __restrict__ ow, const float* __restrict__ ob, float* __restrict__ out)
{
    __shared__ __align__(16) char sm[49152];
    const uint32_t sb = smem_to_u32(sm);
    char* AH = sm;          char* AL = sm + 16384;
    char* BH = sm + 32768;  char* BL = sm + 40960;

    const int tid = threadIdx.x;
    const int lane = tid & 31, w = tid >> 5;
    const int c0 = blockIdx.x * 64, r0 = blockIdx.y * 128;

    float acc[8][4];
#pragma unroll
    for (int i = 0; i < 8; i++) { acc[i][0]=0.f; acc[i][1]=0.f; acc[i][2]=0.f; acc[i][3]=0.f; }

    const uint32_t ssel = (uint32_t)(((lane >> 3) & 1) * 16);

    for (int k0 = 0; k0 < DM; k0 += 32) {
#pragma unroll
        for (int t = 0; t < 2; t++) {
            int p = tid + t * 256;
            int row = p >> 2, ch = p & 3;
            uint32_t off = (uint32_t)row * 128 + (((uint32_t)ch * 16) ^ ((uint32_t)(row & 7) * 16));
            stage8(g_o + (size_t)(r0 + row) * DM + k0 + ch * 8, AH + off, AL + off);
        }
        {
            int p = tid;
            int row = p >> 2, ch = p & 3;
            uint32_t off = (uint32_t)row * 128 + (((uint32_t)ch * 16) ^ ((uint32_t)(row & 7) * 16));
            stage8(ow + (size_t)(c0 + row) * DM + k0 + ch * 8, BH + off, BL + off);
        }
        __syncthreads();

#pragma unroll
        for (int kb = 0; kb < 2; kb++) {
            int r = w * 16 + (lane & 15);
            uint32_t aoff = (uint32_t)r * 128 +
                (((uint32_t)(kb * 32 + ((lane >> 4) * 16))) ^ ((uint32_t)(r & 7) * 16));
            uint32_t ah[4], al[4];
            LDMX4(ah, sb + (uint32_t)(AH - sm) + aoff);
            LDMX4(al, sb + (uint32_t)(AL - sm) + aoff);
#pragma unroll
            for (int nt = 0; nt < 8; nt++) {
                int n = nt * 8 + (lane & 7);
                uint32_t boff = (uint32_t)n * 128 +
                    (((uint32_t)(kb * 32) + ssel) ^ ((uint32_t)(n & 7) * 16));
                uint32_t bh0, bh1, bl0, bl1;
                LDMX2(bh0, bh1, sb + (uint32_t)(BH - sm) + boff);
                LDMX2(bl0, bl1, sb + (uint32_t)(BL - sm) + boff);
                MMA16816(acc[nt], ah, bh0, bh1);
                MMA16816(acc[nt], al, bh0, bh1);
                MMA16816(acc[nt], ah, bl0, bl1);
            }
        }
        __syncthreads();
    }

    const int gr0 = r0 + w * 16 + (lane >> 2);
    const int cq = 2 * (lane & 3);
#pragma unroll
    for (int rr = 0; rr < 2; rr++) {
        int gr = gr0 + rr * 8;
        float* orow = out + (size_t)gr * DM + c0;
#pragma unroll
        for (int nt = 0; nt < 8; nt++) {
            int col = nt * 8 + cq;
            float2 bias = *(const float2*)(ob + c0 + col);
            *(float2*)(orow + col) = make_float2(acc[nt][2 * rr] + bias.x,
                                                 acc[nt][2 * rr + 1] + bias.y);
        }
    }
}

// ---------------------------------------------------------------------------
extern "C" void kernel_launch(void* const* d_in, const int* in_sizes, int n_in,
                              void* d_out, int out_size)
{
    const float* q      = (const float*)d_in[0];
    const float* k      = (const float*)d_in[1];
    const float* v      = (const float*)d_in[2];
    const float* coords = (const float*)d_in[3];
    const unsigned char* kpm = (const unsigned char*)d_in[4];
    const float* qp     = (const float*)d_in[5];
    const float* kpj    = (const float*)d_in[6];
    const float* vp     = (const float*)d_in[7];
    const float* ow     = (const float*)d_in[8];
    const float* ob     = (const float*)d_in[9];
    float* out = (float*)d_out;

    static int attr_set = 0;
    if (!attr_set) {
        cudaFuncSetAttribute(proj_mma_kernel, cudaFuncAttributeMaxDynamicSharedMemorySize, PROJ_SMEM);
        cudaFuncSetAttribute(attn_mma_kernel, cudaFuncAttributeMaxDynamicSharedMemorySize, ATTN_SMEM);
        attr_set = 1;
    }

    presplit_x_kernel<<<dim3(1024, 3), 256>>>(q, k, v);
    presplit_w_kernel<<<dim3(128, 3), 256>>>(qp, kpj, vp);
    proj_mma_kernel<<<dim3(4, 32, 3), 256, PROJ_SMEM>>>();
    attn_mma_kernel<<<dim3(NTOK / 64, NH, B_SZ), 128, ATTN_SMEM>>>(coords, kpm);
    outproj_mma_kernel<<<dim3(8, 32), 256>>>(ow, ob, out);
}